// round 5
// baseline (speedup 1.0000x reference)
#include <cuda_runtime.h>
#include <cuda_bf16.h>
#include <cstdint>

#define GRID_W 112
#define HW (GRID_W*GRID_W)
#define NV 512
#define NP 128
#define M (NP*NV)        /* 65536 rows */
#define S 128

// ---------------------------------------------------------------------------
// Warp-level MMA helpers (sm_80+ PTX)
// ---------------------------------------------------------------------------
__device__ __forceinline__ uint32_t smem_u32(const void* p) {
    uint32_t a;
    asm("{ .reg .u64 t; cvta.to.shared.u64 t, %1; cvt.u32.u64 %0, t; }" : "=r"(a) : "l"(p));
    return a;
}
__device__ __forceinline__ void ldmx4(uint32_t* r, uint32_t addr) {
    asm volatile("ldmatrix.sync.aligned.m8n8.x4.shared.b16 {%0,%1,%2,%3}, [%4];"
        : "=r"(r[0]), "=r"(r[1]), "=r"(r[2]), "=r"(r[3]) : "r"(addr));
}
__device__ __forceinline__ void mma16816(float* d, const uint32_t* a,
                                         uint32_t b0, uint32_t b1) {
    asm volatile(
        "mma.sync.aligned.m16n8k16.row.col.f32.bf16.bf16.f32 "
        "{%0,%1,%2,%3}, {%4,%5,%6,%7}, {%8,%9}, {%0,%1,%2,%3};"
        : "+f"(d[0]), "+f"(d[1]), "+f"(d[2]), "+f"(d[3])
        : "r"(a[0]), "r"(a[1]), "r"(a[2]), "r"(a[3]), "r"(b0), "r"(b1));
}

// ---------------------------------------------------------------------------
// Scratch globals
// ---------------------------------------------------------------------------
__device__ float g_polyA[(size_t)M*2];
__device__ float g_polyB[(size_t)M*2];
__device__ __align__(16) __nv_bfloat16 g_w1sT[3*128*64];   // [step][n][k]
__device__ __align__(16) __nv_bfloat16 g_w1nT[3*128*64];
__device__ __align__(16) __nv_bfloat16 g_w2sT[3*128*128];
__device__ __align__(16) __nv_bfloat16 g_w2nT[3*128*128];
__device__ float g_pw[3*4*128];  // poly-weight rows: Ws[64],Ws[65],Wn[64],Wn[65]

// ---------------------------------------------------------------------------
// Prep: transpose + bf16-convert weights (once per launch; grid=3 steps)
// ---------------------------------------------------------------------------
__global__ void prep_kernel(const float* __restrict__ W1s, const float* __restrict__ W1n,
                            const float* __restrict__ W2s, const float* __restrict__ W2n)
{
    int i = blockIdx.x;
    int tid = threadIdx.x;
    const float* w1s = W1s + (size_t)i*66*128;
    const float* w1n = W1n + (size_t)i*66*128;
    for (int idx = tid; idx < 128*64; idx += 256) {
        int n = idx >> 6, k = idx & 63;
        g_w1sT[(size_t)i*8192 + idx] = __float2bfloat16(w1s[k*128 + n]);
        g_w1nT[(size_t)i*8192 + idx] = __float2bfloat16(w1n[k*128 + n]);
    }
    if (tid < 128) {
        g_pw[i*512 +       tid] = w1s[64*128 + tid];
        g_pw[i*512 + 128 + tid] = w1s[65*128 + tid];
        g_pw[i*512 + 256 + tid] = w1n[64*128 + tid];
        g_pw[i*512 + 384 + tid] = w1n[65*128 + tid];
    }
    const float* w2s = W2s + (size_t)i*128*128;
    const float* w2n = W2n + (size_t)i*128*128;
    for (int idx = tid; idx < 128*128; idx += 256) {
        int n = idx >> 7, k = idx & 127;
        g_w2sT[(size_t)i*16384 + idx] = __float2bfloat16(w2s[k*128 + n]);
        g_w2nT[(size_t)i*16384 + idx] = __float2bfloat16(w2n[k*128 + n]);
    }
}

// ---------------------------------------------------------------------------
// Fused step kernel: sample -> GEMM1(+halo rows) -> stencil -> GEMM2 -> FC
// Block = 128 output rows. 8 warps (4m x 2n), warp tile 32x64.
//
// SMEM map (byte offsets), phases alias dead regions:
//   [0, 36992)        W1s(18432)+W1n(18432)  -->  Hs (h1 rows -2..129, 132xLDH)
//   [36992, 58304)    Xs: 148 x LDX1 (rows -4..131 sampled; 136..147 zeroed)
//   [58304, 79040)    Xn: 144 x LDX1          } --> Hn (128 x LDH) aliases
//   [79040, 113856)   W2s: 128 x LDH
//   [113856, 148672)  W2n: 128 x LDH
//   [148672, 155904)  scalars: PW|B1|B2|FC|PP|RED
// ---------------------------------------------------------------------------
#define LDX1 144
#define LDH  272
#define SM_W1S   0
#define SM_W1N   18432
#define SM_HS    0
#define SM_XS    36992
#define SM_XN    58304
#define SM_HN    36992
#define SM_W2S   79040
#define SM_W2N   113856
#define SM_PW    148672
#define SM_B1    150720
#define SM_B2    151232
#define SM_FC    151744
#define SM_PP    152768   /* 136*2 f32 (poly rows -4..131) */
#define SM_RED   153856   /* 128*4 f32 */
#define SM_TOTAL 155904

__global__ void __launch_bounds__(256, 1)
step_kernel(const float* __restrict__ feature,
            const float* __restrict__ poly_in,
            float* __restrict__ poly_out,
            const float* __restrict__ b1_g,
            const float* __restrict__ b2_g,
            const float* __restrict__ wfc_g,
            const float* __restrict__ bfc_g,
            int step)
{
    extern __shared__ char sm[];
    uint32_t sb = smem_u32(sm);
    int tid = threadIdx.x, wid = tid >> 5, lane = tid & 31;
    int r0 = blockIdx.x * 128;
    int n0 = r0 & (NV-1);
    int pbase = r0 - n0;

    // ---------------- Phase 1: fills ----------------
    // weights
    {
        const uint4* w1sv = (const uint4*)(g_w1sT + (size_t)step*8192);
        const uint4* w1nv = (const uint4*)(g_w1nT + (size_t)step*8192);
        for (int idx = tid; idx < 128*8; idx += 256) {
            int r = idx >> 3, q = idx & 7;
            *(uint4*)(sm + SM_W1S + r*LDX1 + q*16) = w1sv[idx];
            *(uint4*)(sm + SM_W1N + r*LDX1 + q*16) = w1nv[idx];
        }
        const uint4* w2sv = (const uint4*)(g_w2sT + (size_t)step*16384);
        const uint4* w2nv = (const uint4*)(g_w2nT + (size_t)step*16384);
        for (int idx = tid; idx < 128*16; idx += 256) {
            int r = idx >> 4, q = idx & 15;
            *(uint4*)(sm + SM_W2S + r*LDH + q*16) = w2sv[idx];
            *(uint4*)(sm + SM_W2N + r*LDH + q*16) = w2nv[idx];
        }
    }
    // scalars
    for (int idx = tid; idx < 512; idx += 256) ((float*)(sm + SM_PW))[idx] = g_pw[step*512 + idx];
    if (tid < 128) {
        ((float*)(sm + SM_B1))[tid] = b1_g[tid];
        ((float*)(sm + SM_B2))[tid] = b2_g[tid];
    }
    for (int idx = tid; idx < 256; idx += 256) ; // (no-op keep)
    if (tid < 256) ((float*)(sm + SM_FC))[tid] = wfc_g[tid];
    for (int idx = tid; idx < 272; idx += 256) {
        int rr = idx >> 1, c = idx & 1;
        int g = pbase + ((n0 + rr - 4 + NV) & (NV-1));
        ((float*)(sm + SM_PP))[idx] = poly_in[(size_t)g*2 + c];
    }
    // zero Xs junk rows 136..147
    for (int idx = tid; idx < 12*36; idx += 256) {
        int r = 136 + idx/36, w = idx%36;
        *(uint32_t*)(sm + SM_XS + r*LDX1 + w*4) = 0;
    }
    // sample feature rows -4..131 directly into Xs (bf16)
    for (int idx = tid; idx < 136*32; idx += 256) {
        int i = idx >> 5, c2 = idx & 31;
        int g = pbase + ((n0 + i - 4 + NV) & (NV-1));
        float px = poly_in[(size_t)g*2], py = poly_in[(size_t)g*2+1];
        const float2* fb = (const float2*)(feature + (size_t)(g >> 9) * HW * 64);
        float2 val;
        if (step == 0) {
            int xi = (int)fminf(fmaxf(floorf(px*GRID_W), 0.f), 111.f);
            int yi = (int)fminf(fmaxf(floorf(py*GRID_W), 0.f), 111.f);
            val = fb[(size_t)(xi + yi*GRID_W)*32 + c2];
        } else {
            float Xsc = px*GRID_W, Ysc = py*GRID_W;
            float X0 = floorf(Xsc), Y0 = floorf(Ysc);
            float wx = Xsc - X0, wy = Ysc - Y0;
            int x0 = (int)fminf(fmaxf(X0,     0.f), 111.f);
            int x1 = (int)fminf(fmaxf(X0+1.f, 0.f), 111.f);
            int y0 = (int)fminf(fmaxf(Y0,     0.f), 111.f);
            int y1 = (int)fminf(fmaxf(Y0+1.f, 0.f), 111.f);
            float2 m00 = fb[(size_t)(x0 + y0*GRID_W)*32 + c2];
            float2 m01 = fb[(size_t)(x0 + y1*GRID_W)*32 + c2];
            float2 m10 = fb[(size_t)(x1 + y0*GRID_W)*32 + c2];
            float2 m11 = fb[(size_t)(x1 + y1*GRID_W)*32 + c2];
            float w00 = (1.f-wx)*(1.f-wy), w01 = (1.f-wx)*wy;
            float w10 = wx*(1.f-wy),       w11 = wx*wy;
            val.x = w00*m00.x + w01*m01.x + w10*m10.x + w11*m11.x;
            val.y = w00*m00.y + w01*m01.y + w10*m10.y + w11*m11.y;
        }
        __nv_bfloat162 o = __float22bfloat162_rn(val);
        *(uint32_t*)(sm + SM_XS + i*LDX1 + c2*4) = *(uint32_t*)&o;
    }
    __syncthreads();

    // ---------------- Phase 2: Xn ring stencil (rows 0..143) ----------------
    // Xn[j] = 0.25*(Xs[j]+Xs[j+1]+Xs[j+3]+Xs[j+4])  (Xs idx = logical row + 4)
    for (int w = tid; w < 144*32; w += 256) {
        int r = w >> 5, cw = w & 31;
        float sx = 0.f, sy = 0.f;
        #pragma unroll
        for (int d = 0; d < 4; d++) {
            static const int doff[4] = {0, 1, 3, 4};
            uint32_t v = *(uint32_t*)(sm + SM_XS + (r + doff[d])*LDX1 + cw*4);
            float2 f = __bfloat1622float2(*(__nv_bfloat162*)&v);
            sx += f.x; sy += f.y;
        }
        __nv_bfloat162 o = __float22bfloat162_rn(make_float2(0.25f*sx, 0.25f*sy));
        *(uint32_t*)(sm + SM_XN + r*LDX1 + cw*4) = *(uint32_t*)&o;
    }
    __syncthreads();

    // ---------------- Phase 3: MMA1 (h1 rows -2..129, local hr 0..131) -------
    int wm = wid & 3, wn = wid >> 2;
    int l7 = lane & 7, l8 = (lane >> 3) & 1, l16 = (lane >> 4) & 1;
    float acc1[2][8][4];
    float accH[8][4];   // halo m-tile (hr 128..143), only wm==0 warps use it
    #pragma unroll
    for (int mf = 0; mf < 2; mf++)
        #pragma unroll
        for (int nf = 0; nf < 8; nf++)
            #pragma unroll
            for (int j = 0; j < 4; j++) { acc1[mf][nf][j] = 0.f; if (mf==0) accH[nf][j] = 0.f; }

    #pragma unroll
    for (int pass = 0; pass < 2; pass++) {
        // pass0: self term, A row hr -> Xs row hr+2 ; pass1: neighbor term, Xn row hr
        uint32_t xbase = sb + (pass ? SM_XN : (SM_XS + 2*LDX1));
        uint32_t wbase = sb + (pass ? SM_W1N : SM_W1S);
        #pragma unroll
        for (int kt = 0; kt < 4; kt++) {
            uint32_t a[2][4], ah[4];
            #pragma unroll
            for (int mf = 0; mf < 2; mf++)
                ldmx4(a[mf], xbase + (wm*32 + mf*16 + l7 + l8*8)*LDX1 + l16*16 + kt*32);
            if (wm == 0)
                ldmx4(ah, xbase + (128 + l7 + l8*8)*LDX1 + l16*16 + kt*32);
            #pragma unroll
            for (int nf2 = 0; nf2 < 4; nf2++) {
                uint32_t b[4];
                ldmx4(b, wbase + (wn*64 + nf2*16 + l16*8 + l7)*LDX1 + kt*32 + l8*16);
                #pragma unroll
                for (int mf = 0; mf < 2; mf++) {
                    mma16816(acc1[mf][2*nf2],   a[mf], b[0], b[1]);
                    mma16816(acc1[mf][2*nf2+1], a[mf], b[2], b[3]);
                }
                if (wm == 0) {
                    mma16816(accH[2*nf2],   ah, b[0], b[1]);
                    mma16816(accH[2*nf2+1], ah, b[2], b[3]);
                }
            }
        }
    }
    __syncthreads();   // W1/Xs/Xn reads done -> safe to overwrite with Hs

    // ---------------- Phase 4: epilogue1 -> Hs (bf16, rows hr 0..131) --------
    {
        const float* PP = (const float*)(sm + SM_PP);
        const float* B  = (const float*)(sm + SM_B1);
        const float* PW = (const float*)(sm + SM_PW);
        int rlo = lane >> 2, qc = (lane & 3)*2;
        #pragma unroll
        for (int mf = 0; mf < 3; mf++) {
            if (mf == 2 && wm != 0) break;
            int hr = (mf == 2) ? (128 + rlo) : (wm*32 + mf*16 + rlo);
            bool v0 = (mf < 2) || (rlo < 4);          // row hr valid
            bool v1 = (mf < 2);                       // row hr+8 valid
            const float (*A0)[4] = (mf == 2) ? accH : acc1[mf];
            // poly rank-2 coefficients (PP idx = hr + {2 self; 0,1,3,4 nbrs})
            float px0=0,py0=0,ax0=0,ay0=0,px1=0,py1=0,ax1=0,ay1=0;
            if (v0) {
                px0 = PP[(hr+2)*2]; py0 = PP[(hr+2)*2+1];
                ax0 = 0.25f*(PP[hr*2]   + PP[(hr+1)*2]   + PP[(hr+3)*2]   + PP[(hr+4)*2]);
                ay0 = 0.25f*(PP[hr*2+1] + PP[(hr+1)*2+1] + PP[(hr+3)*2+1] + PP[(hr+4)*2+1]);
            }
            int r1 = hr + 8;
            if (v1) {
                px1 = PP[(r1+2)*2]; py1 = PP[(r1+2)*2+1];
                ax1 = 0.25f*(PP[r1*2]   + PP[(r1+1)*2]   + PP[(r1+3)*2]   + PP[(r1+4)*2]);
                ay1 = 0.25f*(PP[r1*2+1] + PP[(r1+1)*2+1] + PP[(r1+3)*2+1] + PP[(r1+4)*2+1]);
            }
            #pragma unroll
            for (int nf = 0; nf < 8; nf++) {
                int n = wn*64 + nf*8 + qc;
                float b0 = B[n],   w0x = PW[n],   w0y = PW[128+n],   w0ax = PW[256+n],   w0ay = PW[384+n];
                float b1 = B[n+1], w1x = PW[n+1], w1y = PW[128+n+1], w1ax = PW[256+n+1], w1ay = PW[384+n+1];
                if (v0) {
                    float v00 = A0[nf][0] + b0 + px0*w0x + py0*w0y + ax0*w0ax + ay0*w0ay;
                    float v01 = A0[nf][1] + b1 + px0*w1x + py0*w1y + ax0*w1ax + ay0*w1ay;
                    __nv_bfloat162 h0 = __float22bfloat162_rn(make_float2(fmaxf(v00,0.f), fmaxf(v01,0.f)));
                    *(uint32_t*)(sm + SM_HS + hr*LDH + n*2) = *(uint32_t*)&h0;
                }
                if (v1) {
                    float v10 = A0[nf][2] + b0 + px1*w0x + py1*w0y + ax1*w0ax + ay1*w0ay;
                    float v11 = A0[nf][3] + b1 + px1*w1x + py1*w1y + ax1*w1ax + ay1*w1ay;
                    __nv_bfloat162 h1 = __float22bfloat162_rn(make_float2(fmaxf(v10,0.f), fmaxf(v11,0.f)));
                    *(uint32_t*)(sm + SM_HS + r1*LDH + n*2) = *(uint32_t*)&h1;
                }
            }
        }
    }
    __syncthreads();

    // ---------------- Phase 5: Hn ring stencil (rows 0..127) -----------------
    // Hn[r] = 0.25*(Hs[r]+Hs[r+1]+Hs[r+3]+Hs[r+4])   (Hs idx = out row + 2)
    for (int w = tid; w < 128*64; w += 256) {
        int r = w >> 6, cw = w & 63;
        float sx = 0.f, sy = 0.f;
        #pragma unroll
        for (int d = 0; d < 4; d++) {
            static const int doff[4] = {0, 1, 3, 4};
            uint32_t v = *(uint32_t*)(sm + SM_HS + (r + doff[d])*LDH + cw*4);
            float2 f = __bfloat1622float2(*(__nv_bfloat162*)&v);
            sx += f.x; sy += f.y;
        }
        __nv_bfloat162 o = __float22bfloat162_rn(make_float2(0.25f*sx, 0.25f*sy));
        *(uint32_t*)(sm + SM_HN + r*LDH + cw*4) = *(uint32_t*)&o;
    }
    __syncthreads();

    // ---------------- Phase 6: MMA2 (both passes, weights preloaded) ---------
    float acc2[2][8][4];
    #pragma unroll
    for (int mf = 0; mf < 2; mf++)
        #pragma unroll
        for (int nf = 0; nf < 8; nf++)
            #pragma unroll
            for (int j = 0; j < 4; j++) acc2[mf][nf][j] = 0.f;

    #pragma unroll
    for (int pass = 0; pass < 2; pass++) {
        uint32_t xbase = sb + (pass ? SM_HN : (SM_HS + 2*LDH));
        uint32_t wbase = sb + (pass ? SM_W2N : SM_W2S);
        #pragma unroll
        for (int kt = 0; kt < 8; kt++) {
            uint32_t a[2][4];
            #pragma unroll
            for (int mf = 0; mf < 2; mf++)
                ldmx4(a[mf], xbase + (wm*32 + mf*16 + l7 + l8*8)*LDH + l16*16 + kt*32);
            #pragma unroll
            for (int nf2 = 0; nf2 < 4; nf2++) {
                uint32_t b[4];
                ldmx4(b, wbase + (wn*64 + nf2*16 + l16*8 + l7)*LDH + kt*32 + l8*16);
                #pragma unroll
                for (int mf = 0; mf < 2; mf++) {
                    mma16816(acc2[mf][2*nf2],   a[mf], b[0], b[1]);
                    mma16816(acc2[mf][2*nf2+1], a[mf], b[2], b[3]);
                }
            }
        }
    }

    // ---------------- Phase 7: relu + FC(128->2) + poly update ---------------
    {
        const float* B  = (const float*)(sm + SM_B2);
        const float* FC = (const float*)(sm + SM_FC);
        int rlo = lane >> 2, qc = (lane & 3)*2;
        float pr[2][2][2];
        #pragma unroll
        for (int mf = 0; mf < 2; mf++)
            #pragma unroll
            for (int rh = 0; rh < 2; rh++) { pr[mf][rh][0] = 0.f; pr[mf][rh][1] = 0.f; }
        #pragma unroll
        for (int mf = 0; mf < 2; mf++)
            #pragma unroll
            for (int nf = 0; nf < 8; nf++) {
                int n = wn*64 + nf*8 + qc;
                float b0 = B[n], b1 = B[n+1];
                float h00 = fmaxf(acc2[mf][nf][0] + b0, 0.f);
                float h01 = fmaxf(acc2[mf][nf][1] + b1, 0.f);
                float h10 = fmaxf(acc2[mf][nf][2] + b0, 0.f);
                float h11 = fmaxf(acc2[mf][nf][3] + b1, 0.f);
                float f0x = FC[n*2], f0y = FC[n*2+1], f1x = FC[(n+1)*2], f1y = FC[(n+1)*2+1];
                pr[mf][0][0] += h00*f0x + h01*f1x;  pr[mf][0][1] += h00*f0y + h01*f1y;
                pr[mf][1][0] += h10*f0x + h11*f1x;  pr[mf][1][1] += h10*f0y + h11*f1y;
            }
        #pragma unroll
        for (int mf = 0; mf < 2; mf++)
            #pragma unroll
            for (int rh = 0; rh < 2; rh++)
                #pragma unroll
                for (int j = 0; j < 2; j++) {
                    pr[mf][rh][j] += __shfl_xor_sync(0xffffffffu, pr[mf][rh][j], 1);
                    pr[mf][rh][j] += __shfl_xor_sync(0xffffffffu, pr[mf][rh][j], 2);
                }
        float* RED = (float*)(sm + SM_RED);
        if ((lane & 3) == 0) {
            #pragma unroll
            for (int mf = 0; mf < 2; mf++)
                #pragma unroll
                for (int rh = 0; rh < 2; rh++) {
                    int row = wm*32 + mf*16 + rh*8 + rlo;
                    RED[row*4 + wn*2 + 0] = pr[mf][rh][0];
                    RED[row*4 + wn*2 + 1] = pr[mf][rh][1];
                }
        }
        __syncthreads();
        {
            int row = tid >> 1, j = tid & 1;
            float s = RED[row*4 + j] + RED[row*4 + 2 + j] + bfc_g[j];
            poly_out[(size_t)(r0 + row)*2 + j] =
                ((const float*)(sm + SM_PP))[(row + 4)*2 + j] + s;
        }
    }
}

// ---------------------------------------------------------------------------
extern "C" void kernel_launch(void* const* d_in, const int* in_sizes, int n_in,
                              void* d_out, int out_size)
{
    const float* feature    = (const float*)d_in[0];
    const float* init_polys = (const float*)d_in[1];
    /* d_in[2] = adj (fixed ring graph -> stencil) */
    const float* W1s = (const float*)d_in[3];
    const float* W1n = (const float*)d_in[4];
    const float* b1  = (const float*)d_in[5];
    const float* W2s = (const float*)d_in[6];
    const float* W2n = (const float*)d_in[7];
    const float* b2  = (const float*)d_in[8];
    const float* Wfc = (const float*)d_in[9];
    const float* bfc = (const float*)d_in[10];

    cudaFuncSetAttribute(step_kernel, cudaFuncAttributeMaxDynamicSharedMemorySize, SM_TOTAL);

    float *polyA, *polyB;
    cudaGetSymbolAddress((void**)&polyA, g_polyA);
    cudaGetSymbolAddress((void**)&polyB, g_polyB);

    prep_kernel<<<3, 256>>>(W1s, W1n, W2s, W2n);

    float* pouts[3] = { polyA, polyB, (float*)d_out };
    const float* pin = init_polys;
    for (int i = 0; i < 3; i++) {
        step_kernel<<<M/128, 256, SM_TOTAL>>>(feature, pin, pouts[i],
                                              b1 + i*S, b2 + i*S,
                                              Wfc + i*S*2, bfc + i*2, i);
        pin = pouts[i];
    }
}

// round 7
// speedup vs baseline: 1.2549x; 1.2549x over previous
#include <cuda_runtime.h>
#include <cuda_bf16.h>
#include <cstdint>

#define GRID_W 112
#define HW (GRID_W*GRID_W)
#define NV 512
#define NP 128
#define M (NP*NV)        /* 65536 rows */
#define S 128

// ---------------------------------------------------------------------------
// Warp-level MMA helpers (sm_80+ PTX)
// ---------------------------------------------------------------------------
__device__ __forceinline__ uint32_t smem_u32(const void* p) {
    uint32_t a;
    asm("{ .reg .u64 t; cvta.to.shared.u64 t, %1; cvt.u32.u64 %0, t; }" : "=r"(a) : "l"(p));
    return a;
}
__device__ __forceinline__ void ldmx4(uint32_t* r, uint32_t addr) {
    asm volatile("ldmatrix.sync.aligned.m8n8.x4.shared.b16 {%0,%1,%2,%3}, [%4];"
        : "=r"(r[0]), "=r"(r[1]), "=r"(r[2]), "=r"(r[3]) : "r"(addr));
}
__device__ __forceinline__ void mma16816(float* d, const uint32_t* a,
                                         uint32_t b0, uint32_t b1) {
    asm volatile(
        "mma.sync.aligned.m16n8k16.row.col.f32.bf16.bf16.f32 "
        "{%0,%1,%2,%3}, {%4,%5,%6,%7}, {%8,%9}, {%0,%1,%2,%3};"
        : "+f"(d[0]), "+f"(d[1]), "+f"(d[2]), "+f"(d[3])
        : "r"(a[0]), "r"(a[1]), "r"(a[2]), "r"(a[3]), "r"(b0), "r"(b1));
}

// ---------------------------------------------------------------------------
// Scratch globals
// ---------------------------------------------------------------------------
__device__ __align__(16) __nv_bfloat16 g_featb[(size_t)M*64];   // sampled features
__device__ float g_polyA[(size_t)M*2];
__device__ float g_polyB[(size_t)M*2];
__device__ __align__(16) __nv_bfloat16 g_w1sT[3*128*64];   // [step][n][k]
__device__ __align__(16) __nv_bfloat16 g_w1nT[3*128*64];
__device__ __align__(16) __nv_bfloat16 g_w2sT[3*128*128];
__device__ __align__(16) __nv_bfloat16 g_w2nT[3*128*128];
__device__ float g_pw[3*4*128];  // poly-weight rows: Ws[64],Ws[65],Wn[64],Wn[65]

// ---------------------------------------------------------------------------
// Prep: transpose + bf16-convert weights (once per launch; grid=3 steps)
// ---------------------------------------------------------------------------
__global__ void prep_kernel(const float* __restrict__ W1s, const float* __restrict__ W1n,
                            const float* __restrict__ W2s, const float* __restrict__ W2n)
{
    int i = blockIdx.x;
    int tid = threadIdx.x;
    const float* w1s = W1s + (size_t)i*66*128;
    const float* w1n = W1n + (size_t)i*66*128;
    for (int idx = tid; idx < 128*64; idx += 256) {
        int n = idx >> 6, k = idx & 63;
        g_w1sT[(size_t)i*8192 + idx] = __float2bfloat16(w1s[k*128 + n]);
        g_w1nT[(size_t)i*8192 + idx] = __float2bfloat16(w1n[k*128 + n]);
    }
    if (tid < 128) {
        g_pw[i*512 +       tid] = w1s[64*128 + tid];
        g_pw[i*512 + 128 + tid] = w1s[65*128 + tid];
        g_pw[i*512 + 256 + tid] = w1n[64*128 + tid];
        g_pw[i*512 + 384 + tid] = w1n[65*128 + tid];
    }
    const float* w2s = W2s + (size_t)i*128*128;
    const float* w2n = W2n + (size_t)i*128*128;
    for (int idx = tid; idx < 128*128; idx += 256) {
        int n = idx >> 7, k = idx & 127;
        g_w2sT[(size_t)i*16384 + idx] = __float2bfloat16(w2s[k*128 + n]);
        g_w2nT[(size_t)i*16384 + idx] = __float2bfloat16(w2n[k*128 + n]);
    }
}

// ---------------------------------------------------------------------------
// Sampler: gather features at poly coords -> g_featb [M,64] bf16
// block (16,16): tx = float4 chunk (16 ch), ty = vertex. High occupancy.
// ---------------------------------------------------------------------------
__global__ void sample_kernel(const float* __restrict__ feature,
                              const float* __restrict__ poly, int step)
{
    int v  = blockIdx.x * 16 + threadIdx.y;
    int c4 = threadIdx.x;               // 0..15 (4 floats each)
    int p  = v >> 9;
    float px = poly[v*2+0];
    float py = poly[v*2+1];
    const float4* fb = (const float4*)(feature + (size_t)p * HW * 64);
    float4 val;
    if (step == 0) {
        int xi = (int)fminf(fmaxf(floorf(px*GRID_W), 0.f), 111.f);
        int yi = (int)fminf(fmaxf(floorf(py*GRID_W), 0.f), 111.f);
        val = fb[(size_t)(xi + yi*GRID_W)*16 + c4];
    } else {
        float Xs = px*GRID_W, Ys = py*GRID_W;
        float X0 = floorf(Xs), Y0 = floorf(Ys);
        float wx = Xs - X0, wy = Ys - Y0;
        int x0 = (int)fminf(fmaxf(X0,     0.f), 111.f);
        int x1 = (int)fminf(fmaxf(X0+1.f, 0.f), 111.f);
        int y0 = (int)fminf(fmaxf(Y0,     0.f), 111.f);
        int y1 = (int)fminf(fmaxf(Y0+1.f, 0.f), 111.f);
        float4 m00 = fb[(size_t)(x0 + y0*GRID_W)*16 + c4];
        float4 m01 = fb[(size_t)(x0 + y1*GRID_W)*16 + c4];
        float4 m10 = fb[(size_t)(x1 + y0*GRID_W)*16 + c4];
        float4 m11 = fb[(size_t)(x1 + y1*GRID_W)*16 + c4];
        float w00 = (1.f-wx)*(1.f-wy), w01 = (1.f-wx)*wy;
        float w10 = wx*(1.f-wy),       w11 = wx*wy;
        val.x = w00*m00.x + w01*m01.x + w10*m10.x + w11*m11.x;
        val.y = w00*m00.y + w01*m01.y + w10*m10.y + w11*m11.y;
        val.z = w00*m00.z + w01*m01.z + w10*m10.z + w11*m11.z;
        val.w = w00*m00.w + w01*m01.w + w10*m10.w + w11*m11.w;
    }
    __nv_bfloat162 o0 = __float22bfloat162_rn(make_float2(val.x, val.y));
    __nv_bfloat162 o1 = __float22bfloat162_rn(make_float2(val.z, val.w));
    *(uint2*)(g_featb + (size_t)v*64 + c4*4) =
        make_uint2(*(uint32_t*)&o0, *(uint32_t*)&o1);
}

// ---------------------------------------------------------------------------
// Fused GEMM kernel: GEMM1(+halo rows) -> stencil -> GEMM2 -> FC -> poly upd
// Block = 128 output rows, 512 threads, 16 warps (4m x 4n), warp tile 32x32.
//
// SMEM map (byte offsets), phases alias dead regions:
//   [0, 36992)        W1s(18432)+W1n(18432)  -->  Hs (h1 rows -2..129+, 144xLDH? no: 132 used)
//   [36992, 58304)    Xs: 148 x LDX1 (rows -4..131; 136..147 zeroed)
//   [58304, 79040)    Xn: 144 x LDX1          --> Hn (128 x LDH) aliases
//   [79040, 113856)   W2s: 128 x LDH
//   [113856, 148672)  W2n: 128 x LDH
//   [148672, 157952)  scalars: PW|B1|B2|FC|PP|RED
// ---------------------------------------------------------------------------
#define LDX1 144
#define LDH  272
#define SM_W1S   0
#define SM_W1N   18432
#define SM_HS    0
#define SM_XS    36992
#define SM_XN    58304
#define SM_HN    36992
#define SM_W2S   79040
#define SM_W2N   113856
#define SM_PW    148672
#define SM_B1    150720
#define SM_B2    151232
#define SM_FC    151744
#define SM_PP    152768   /* 136*2 f32 (poly rows -4..131) */
#define SM_RED   153856   /* 128*8 f32 = 4096 */
#define SM_TOTAL 157952

__global__ void __launch_bounds__(512, 1)
gemm12_kernel(const float* __restrict__ poly_in,
              float* __restrict__ poly_out,
              const float* __restrict__ b1_g,
              const float* __restrict__ b2_g,
              const float* __restrict__ wfc_g,
              const float* __restrict__ bfc_g,
              int step)
{
    extern __shared__ char sm[];
    uint32_t sb = smem_u32(sm);
    int tid = threadIdx.x, wid = tid >> 5, lane = tid & 31;
    int r0 = blockIdx.x * 128;
    int n0 = r0 & (NV-1);
    int pbase = r0 - n0;

    // ---------------- Phase 1: fills ----------------
    {
        const uint4* w1sv = (const uint4*)(g_w1sT + (size_t)step*8192);
        const uint4* w1nv = (const uint4*)(g_w1nT + (size_t)step*8192);
        for (int idx = tid; idx < 128*8; idx += 512) {
            int r = idx >> 3, q = idx & 7;
            *(uint4*)(sm + SM_W1S + r*LDX1 + q*16) = w1sv[idx];
            *(uint4*)(sm + SM_W1N + r*LDX1 + q*16) = w1nv[idx];
        }
        const uint4* w2sv = (const uint4*)(g_w2sT + (size_t)step*16384);
        const uint4* w2nv = (const uint4*)(g_w2nT + (size_t)step*16384);
        for (int idx = tid; idx < 128*16; idx += 512) {
            int r = idx >> 4, q = idx & 15;
            *(uint4*)(sm + SM_W2S + r*LDH + q*16) = w2sv[idx];
            *(uint4*)(sm + SM_W2N + r*LDH + q*16) = w2nv[idx];
        }
        // Xs rows -4..131 from g_featb (coalesced), wrap within polygon
        const uint4* featv = (const uint4*)g_featb;
        for (int idx = tid; idx < 136*8; idx += 512) {
            int r = idx >> 3, q = idx & 7;
            int n = (n0 + r - 4 + NV) & (NV-1);
            *(uint4*)(sm + SM_XS + r*LDX1 + q*16) = featv[(size_t)(pbase + n)*8 + q];
        }
    }
    if (tid < 512) {
        if (tid < 128) {
            ((float*)(sm + SM_B1))[tid] = b1_g[tid];
            ((float*)(sm + SM_B2))[tid] = b2_g[tid];
        }
        if (tid < 256) ((float*)(sm + SM_FC))[tid] = wfc_g[tid];
        ((float*)(sm + SM_PW))[tid] = g_pw[step*512 + tid];
        if (tid < 272) {
            int rr = tid >> 1, c = tid & 1;
            int g = pbase + ((n0 + rr - 4 + NV) & (NV-1));
            ((float*)(sm + SM_PP))[tid] = poly_in[(size_t)g*2 + c];
        }
        // zero Xs junk rows 136..147
        if (tid < 432) {
            int r = 136 + tid/36, w = tid%36;
            *(uint32_t*)(sm + SM_XS + r*LDX1 + w*4) = 0;
        }
    }
    __syncthreads();

    // ---------------- Phase 2: Xn ring stencil (rows 0..143) ----------------
    for (int w = tid; w < 144*32; w += 512) {
        int r = w >> 5, cw = w & 31;
        float sx = 0.f, sy = 0.f;
        #pragma unroll
        for (int d = 0; d < 4; d++) {
            static const int doff[4] = {0, 1, 3, 4};
            uint32_t v = *(uint32_t*)(sm + SM_XS + (r + doff[d])*LDX1 + cw*4);
            float2 f = __bfloat1622float2(*(__nv_bfloat162*)&v);
            sx += f.x; sy += f.y;
        }
        __nv_bfloat162 o = __float22bfloat162_rn(make_float2(0.25f*sx, 0.25f*sy));
        *(uint32_t*)(sm + SM_XN + r*LDX1 + cw*4) = *(uint32_t*)&o;
    }
    __syncthreads();

    // ---------------- Phase 3: MMA1 (h1 local rows 0..143) -------------------
    int wm = wid & 3, wn = wid >> 2;        // 4m x 4n
    int l7 = lane & 7, l8 = (lane >> 3) & 1, l16 = (lane >> 4) & 1;
    float acc1[2][4][4];
    float accH[4][4];    // halo m-tile rows 128..143, wm==0 warps only
    #pragma unroll
    for (int mf = 0; mf < 2; mf++)
        #pragma unroll
        for (int nf = 0; nf < 4; nf++)
            #pragma unroll
            for (int j = 0; j < 4; j++) { acc1[mf][nf][j] = 0.f; if (mf==0) accH[nf][j] = 0.f; }

    #pragma unroll
    for (int pass = 0; pass < 2; pass++) {
        uint32_t xbase = sb + (pass ? SM_XN : (SM_XS + 2*LDX1));
        uint32_t wbase = sb + (pass ? SM_W1N : SM_W1S);
        #pragma unroll
        for (int kt = 0; kt < 4; kt++) {
            uint32_t a[2][4], ah[4];
            #pragma unroll
            for (int mf = 0; mf < 2; mf++)
                ldmx4(a[mf], xbase + (wm*32 + mf*16 + l7 + l8*8)*LDX1 + l16*16 + kt*32);
            if (wm == 0)
                ldmx4(ah, xbase + (128 + l7 + l8*8)*LDX1 + l16*16 + kt*32);
            #pragma unroll
            for (int nf2 = 0; nf2 < 2; nf2++) {
                uint32_t b[4];
                ldmx4(b, wbase + (wn*32 + nf2*16 + l16*8 + l7)*LDX1 + kt*32 + l8*16);
                #pragma unroll
                for (int mf = 0; mf < 2; mf++) {
                    mma16816(acc1[mf][2*nf2],   a[mf], b[0], b[1]);
                    mma16816(acc1[mf][2*nf2+1], a[mf], b[2], b[3]);
                }
                if (wm == 0) {
                    mma16816(accH[2*nf2],   ah, b[0], b[1]);
                    mma16816(accH[2*nf2+1], ah, b[2], b[3]);
                }
            }
        }
    }
    __syncthreads();   // W1/Xs/Xn reads done -> safe to overwrite with Hs

    // ---------------- Phase 4: epilogue1 -> Hs (bf16, rows hr 0..131) --------
    {
        const float* PP = (const float*)(sm + SM_PP);
        const float* B  = (const float*)(sm + SM_B1);
        const float* PW = (const float*)(sm + SM_PW);
        int rlo = lane >> 2, qc = (lane & 3)*2;
        #pragma unroll
        for (int mf = 0; mf < 3; mf++) {
            if (mf == 2 && wm != 0) break;
            int hr = (mf == 2) ? (128 + rlo) : (wm*32 + mf*16 + rlo);
            bool v0 = (mf < 2) || (rlo < 4);
            bool v1 = (mf < 2);
            const float (*A0)[4] = (mf == 2) ? accH : acc1[mf];
            float px0=0,py0=0,ax0=0,ay0=0,px1=0,py1=0,ax1=0,ay1=0;
            if (v0) {
                px0 = PP[(hr+2)*2]; py0 = PP[(hr+2)*2+1];
                ax0 = 0.25f*(PP[hr*2]   + PP[(hr+1)*2]   + PP[(hr+3)*2]   + PP[(hr+4)*2]);
                ay0 = 0.25f*(PP[hr*2+1] + PP[(hr+1)*2+1] + PP[(hr+3)*2+1] + PP[(hr+4)*2+1]);
            }
            int r1 = hr + 8;
            if (v1) {
                px1 = PP[(r1+2)*2]; py1 = PP[(r1+2)*2+1];
                ax1 = 0.25f*(PP[r1*2]   + PP[(r1+1)*2]   + PP[(r1+3)*2]   + PP[(r1+4)*2]);
                ay1 = 0.25f*(PP[r1*2+1] + PP[(r1+1)*2+1] + PP[(r1+3)*2+1] + PP[(r1+4)*2+1]);
            }
            #pragma unroll
            for (int nf = 0; nf < 4; nf++) {
                int n = wn*32 + nf*8 + qc;
                float b0 = B[n],   w0x = PW[n],   w0y = PW[128+n],   w0ax = PW[256+n],   w0ay = PW[384+n];
                float b1 = B[n+1], w1x = PW[n+1], w1y = PW[128+n+1], w1ax = PW[256+n+1], w1ay = PW[384+n+1];
                if (v0) {
                    float v00 = A0[nf][0] + b0 + px0*w0x + py0*w0y + ax0*w0ax + ay0*w0ay;
                    float v01 = A0[nf][1] + b1 + px0*w1x + py0*w1y + ax0*w1ax + ay0*w1ay;
                    __nv_bfloat162 h0 = __float22bfloat162_rn(make_float2(fmaxf(v00,0.f), fmaxf(v01,0.f)));
                    *(uint32_t*)(sm + SM_HS + hr*LDH + n*2) = *(uint32_t*)&h0;
                }
                if (v1) {
                    float v10 = A0[nf][2] + b0 + px1*w0x + py1*w0y + ax1*w0ax + ay1*w0ay;
                    float v11 = A0[nf][3] + b1 + px1*w1x + py1*w1y + ax1*w1ax + ay1*w1ay;
                    __nv_bfloat162 h1 = __float22bfloat162_rn(make_float2(fmaxf(v10,0.f), fmaxf(v11,0.f)));
                    *(uint32_t*)(sm + SM_HS + r1*LDH + n*2) = *(uint32_t*)&h1;
                }
            }
        }
    }
    __syncthreads();

    // ---------------- Phase 5: Hn ring stencil (rows 0..127) -----------------
    for (int w = tid; w < 128*64; w += 512) {
        int r = w >> 6, cw = w & 63;
        float sx = 0.f, sy = 0.f;
        #pragma unroll
        for (int d = 0; d < 4; d++) {
            static const int doff[4] = {0, 1, 3, 4};
            uint32_t v = *(uint32_t*)(sm + SM_HS + (r + doff[d])*LDH + cw*4);
            float2 f = __bfloat1622float2(*(__nv_bfloat162*)&v);
            sx += f.x; sy += f.y;
        }
        __nv_bfloat162 o = __float22bfloat162_rn(make_float2(0.25f*sx, 0.25f*sy));
        *(uint32_t*)(sm + SM_HN + r*LDH + cw*4) = *(uint32_t*)&o;
    }
    __syncthreads();

    // ---------------- Phase 6: MMA2 (both passes, weights preloaded) ---------
    float acc2[2][4][4];
    #pragma unroll
    for (int mf = 0; mf < 2; mf++)
        #pragma unroll
        for (int nf = 0; nf < 4; nf++)
            #pragma unroll
            for (int j = 0; j < 4; j++) acc2[mf][nf][j] = 0.f;

    #pragma unroll
    for (int pass = 0; pass < 2; pass++) {
        uint32_t xbase = sb + (pass ? SM_HN : (SM_HS + 2*LDH));
        uint32_t wbase = sb + (pass ? SM_W2N : SM_W2S);
        #pragma unroll
        for (int kt = 0; kt < 8; kt++) {
            uint32_t a[2][4];
            #pragma unroll
            for (int mf = 0; mf < 2; mf++)
                ldmx4(a[mf], xbase + (wm*32 + mf*16 + l7 + l8*8)*LDH + l16*16 + kt*32);
            #pragma unroll
            for (int nf2 = 0; nf2 < 2; nf2++) {
                uint32_t b[4];
                ldmx4(b, wbase + (wn*32 + nf2*16 + l16*8 + l7)*LDH + kt*32 + l8*16);
                #pragma unroll
                for (int mf = 0; mf < 2; mf++) {
                    mma16816(acc2[mf][2*nf2],   a[mf], b[0], b[1]);
                    mma16816(acc2[mf][2*nf2+1], a[mf], b[2], b[3]);
                }
            }
        }
    }

    // ---------------- Phase 7: relu + FC(128->2) + poly update ---------------
    {
        const float* B  = (const float*)(sm + SM_B2);
        const float* FC = (const float*)(sm + SM_FC);
        int rlo = lane >> 2, qc = (lane & 3)*2;
        float pr[2][2][2];
        #pragma unroll
        for (int mf = 0; mf < 2; mf++)
            #pragma unroll
            for (int rh = 0; rh < 2; rh++) { pr[mf][rh][0] = 0.f; pr[mf][rh][1] = 0.f; }
        #pragma unroll
        for (int mf = 0; mf < 2; mf++)
            #pragma unroll
            for (int nf = 0; nf < 4; nf++) {
                int n = wn*32 + nf*8 + qc;
                float b0 = B[n], b1 = B[n+1];
                float h00 = fmaxf(acc2[mf][nf][0] + b0, 0.f);
                float h01 = fmaxf(acc2[mf][nf][1] + b1, 0.f);
                float h10 = fmaxf(acc2[mf][nf][2] + b0, 0.f);
                float h11 = fmaxf(acc2[mf][nf][3] + b1, 0.f);
                float f0x = FC[n*2], f0y = FC[n*2+1], f1x = FC[(n+1)*2], f1y = FC[(n+1)*2+1];
                pr[mf][0][0] += h00*f0x + h01*f1x;  pr[mf][0][1] += h00*f0y + h01*f1y;
                pr[mf][1][0] += h10*f0x + h11*f1x;  pr[mf][1][1] += h10*f0y + h11*f1y;
            }
        #pragma unroll
        for (int mf = 0; mf < 2; mf++)
            #pragma unroll
            for (int rh = 0; rh < 2; rh++)
                #pragma unroll
                for (int j = 0; j < 2; j++) {
                    pr[mf][rh][j] += __shfl_xor_sync(0xffffffffu, pr[mf][rh][j], 1);
                    pr[mf][rh][j] += __shfl_xor_sync(0xffffffffu, pr[mf][rh][j], 2);
                }
        float* RED = (float*)(sm + SM_RED);
        if ((lane & 3) == 0) {
            #pragma unroll
            for (int mf = 0; mf < 2; mf++)
                #pragma unroll
                for (int rh = 0; rh < 2; rh++) {
                    int row = wm*32 + mf*16 + rh*8 + rlo;
                    RED[row*8 + wn*2 + 0] = pr[mf][rh][0];
                    RED[row*8 + wn*2 + 1] = pr[mf][rh][1];
                }
        }
        __syncthreads();
        if (tid < 256) {
            int row = tid >> 1, j = tid & 1;
            float s = RED[row*8 + j] + RED[row*8 + 2 + j]
                    + RED[row*8 + 4 + j] + RED[row*8 + 6 + j] + bfc_g[j];
            poly_out[(size_t)(r0 + row)*2 + j] =
                ((const float*)(sm + SM_PP))[(row + 4)*2 + j] + s;
        }
    }
}

// ---------------------------------------------------------------------------
extern "C" void kernel_launch(void* const* d_in, const int* in_sizes, int n_in,
                              void* d_out, int out_size)
{
    const float* feature    = (const float*)d_in[0];
    const float* init_polys = (const float*)d_in[1];
    /* d_in[2] = adj (fixed ring graph -> stencil) */
    const float* W1s = (const float*)d_in[3];
    const float* W1n = (const float*)d_in[4];
    const float* b1  = (const float*)d_in[5];
    const float* W2s = (const float*)d_in[6];
    const float* W2n = (const float*)d_in[7];
    const float* b2  = (const float*)d_in[8];
    const float* Wfc = (const float*)d_in[9];
    const float* bfc = (const float*)d_in[10];

    cudaFuncSetAttribute(gemm12_kernel, cudaFuncAttributeMaxDynamicSharedMemorySize, SM_TOTAL);

    float *polyA, *polyB;
    cudaGetSymbolAddress((void**)&polyA, g_polyA);
    cudaGetSymbolAddress((void**)&polyB, g_polyB);

    prep_kernel<<<3, 256>>>(W1s, W1n, W2s, W2n);

    float* pouts[3] = { polyA, polyB, (float*)d_out };
    const float* pin = init_polys;
    for (int i = 0; i < 3; i++) {
        sample_kernel<<<M/16, dim3(16,16)>>>(feature, pin, i);
        gemm12_kernel<<<M/128, 512, SM_TOTAL>>>(pin, pouts[i],
                                                b1 + i*S, b2 + i*S,
                                                Wfc + i*S*2, bfc + i*2, i);
        pin = pouts[i];
    }
}

// round 8
// speedup vs baseline: 1.2880x; 1.0264x over previous
#include <cuda_runtime.h>
#include <cuda_bf16.h>
#include <cstdint>

#define GRID_W 112
#define HW (GRID_W*GRID_W)
#define NV 512
#define NP 128
#define M (NP*NV)        /* 65536 rows */
#define S 128
#define GRID_C 128       /* persistent CTAs */
#define TILES_PER_CTA 4

// ---------------------------------------------------------------------------
// PTX helpers (sm_80+ : valid for compute_103)
// ---------------------------------------------------------------------------
__device__ __forceinline__ uint32_t smem_u32(const void* p) {
    uint32_t a;
    asm("{ .reg .u64 t; cvta.to.shared.u64 t, %1; cvt.u32.u64 %0, t; }" : "=r"(a) : "l"(p));
    return a;
}
__device__ __forceinline__ void ldmx4(uint32_t* r, uint32_t addr) {
    asm volatile("ldmatrix.sync.aligned.m8n8.x4.shared.b16 {%0,%1,%2,%3}, [%4];"
        : "=r"(r[0]), "=r"(r[1]), "=r"(r[2]), "=r"(r[3]) : "r"(addr));
}
__device__ __forceinline__ void mma16816(float* d, const uint32_t* a,
                                         uint32_t b0, uint32_t b1) {
    asm volatile(
        "mma.sync.aligned.m16n8k16.row.col.f32.bf16.bf16.f32 "
        "{%0,%1,%2,%3}, {%4,%5,%6,%7}, {%8,%9}, {%0,%1,%2,%3};"
        : "+f"(d[0]), "+f"(d[1]), "+f"(d[2]), "+f"(d[3])
        : "r"(a[0]), "r"(a[1]), "r"(a[2]), "r"(a[3]), "r"(b0), "r"(b1));
}
#define CP_ASYNC16(dst, src) \
    asm volatile("cp.async.cg.shared.global [%0], [%1], 16;" :: "r"(dst), "l"(src))
#define CP_COMMIT() asm volatile("cp.async.commit_group;")
#define CP_WAIT0()  asm volatile("cp.async.wait_group 0;")

// ---------------------------------------------------------------------------
// Scratch globals
// ---------------------------------------------------------------------------
__device__ __align__(16) __nv_bfloat16 g_featb[(size_t)M*64];   // sampled features
__device__ float g_polyA[(size_t)M*2];
__device__ float g_polyB[(size_t)M*2];
__device__ __align__(16) __nv_bfloat16 g_w1T[3*128*128];   // [step][n][k] k<64:W1s, k>=64:W1n
__device__ __align__(16) __nv_bfloat16 g_w2sT[3*128*128];
__device__ __align__(16) __nv_bfloat16 g_w2nT[3*128*128];
__device__ float g_pw[3*4*128];  // poly-weight rows: Ws[64],Ws[65],Wn[64],Wn[65]

// ---------------------------------------------------------------------------
// Prep: transpose + bf16-convert weights (once per launch; grid=3 steps)
// ---------------------------------------------------------------------------
__global__ void prep_kernel(const float* __restrict__ W1s, const float* __restrict__ W1n,
                            const float* __restrict__ W2s, const float* __restrict__ W2n)
{
    int i = blockIdx.x;
    int tid = threadIdx.x;
    const float* w1s = W1s + (size_t)i*66*128;
    const float* w1n = W1n + (size_t)i*66*128;
    for (int idx = tid; idx < 128*128; idx += 256) {
        int n = idx >> 7, k = idx & 127;
        float v = (k < 64) ? w1s[k*128 + n] : w1n[(k-64)*128 + n];
        g_w1T[(size_t)i*16384 + idx] = __float2bfloat16(v);
    }
    if (tid < 128) {
        g_pw[i*512 +       tid] = w1s[64*128 + tid];
        g_pw[i*512 + 128 + tid] = w1s[65*128 + tid];
        g_pw[i*512 + 256 + tid] = w1n[64*128 + tid];
        g_pw[i*512 + 384 + tid] = w1n[65*128 + tid];
    }
    const float* w2s = W2s + (size_t)i*128*128;
    const float* w2n = W2n + (size_t)i*128*128;
    for (int idx = tid; idx < 128*128; idx += 256) {
        int n = idx >> 7, k = idx & 127;
        g_w2sT[(size_t)i*16384 + idx] = __float2bfloat16(w2s[k*128 + n]);
        g_w2nT[(size_t)i*16384 + idx] = __float2bfloat16(w2n[k*128 + n]);
    }
}

// ---------------------------------------------------------------------------
// Sampler: gather features at poly coords -> g_featb [M,64] bf16
// ---------------------------------------------------------------------------
__global__ void sample_kernel(const float* __restrict__ feature,
                              const float* __restrict__ poly, int step)
{
    int v  = blockIdx.x * 16 + threadIdx.y;
    int c4 = threadIdx.x;               // 0..15 (4 floats each)
    int p  = v >> 9;
    float px = poly[v*2+0];
    float py = poly[v*2+1];
    const float4* fb = (const float4*)(feature + (size_t)p * HW * 64);
    float4 val;
    if (step == 0) {
        int xi = (int)fminf(fmaxf(floorf(px*GRID_W), 0.f), 111.f);
        int yi = (int)fminf(fmaxf(floorf(py*GRID_W), 0.f), 111.f);
        val = fb[(size_t)(xi + yi*GRID_W)*16 + c4];
    } else {
        float Xs = px*GRID_W, Ys = py*GRID_W;
        float X0 = floorf(Xs), Y0 = floorf(Ys);
        float wx = Xs - X0, wy = Ys - Y0;
        int x0 = (int)fminf(fmaxf(X0,     0.f), 111.f);
        int x1 = (int)fminf(fmaxf(X0+1.f, 0.f), 111.f);
        int y0 = (int)fminf(fmaxf(Y0,     0.f), 111.f);
        int y1 = (int)fminf(fmaxf(Y0+1.f, 0.f), 111.f);
        float4 m00 = fb[(size_t)(x0 + y0*GRID_W)*16 + c4];
        float4 m01 = fb[(size_t)(x0 + y1*GRID_W)*16 + c4];
        float4 m10 = fb[(size_t)(x1 + y0*GRID_W)*16 + c4];
        float4 m11 = fb[(size_t)(x1 + y1*GRID_W)*16 + c4];
        float w00 = (1.f-wx)*(1.f-wy), w01 = (1.f-wx)*wy;
        float w10 = wx*(1.f-wy),       w11 = wx*wy;
        val.x = w00*m00.x + w01*m01.x + w10*m10.x + w11*m11.x;
        val.y = w00*m00.y + w01*m01.y + w10*m10.y + w11*m11.y;
        val.z = w00*m00.z + w01*m01.z + w10*m10.z + w11*m11.z;
        val.w = w00*m00.w + w01*m01.w + w10*m10.w + w11*m11.w;
    }
    __nv_bfloat162 o0 = __float22bfloat162_rn(make_float2(val.x, val.y));
    __nv_bfloat162 o1 = __float22bfloat162_rn(make_float2(val.z, val.w));
    *(uint2*)(g_featb + (size_t)v*64 + c4*4) =
        make_uint2(*(uint32_t*)&o0, *(uint32_t*)&o1);
}

// ---------------------------------------------------------------------------
// Persistent fused GEMM kernel. 128 CTAs x 4 tiles, 512 thr, 16 warps (4m x 4n).
// Per tile: XA build(+stencil) -> MMA1(K=128, +halo M-tile) -> epi1 -> Hs
//           -> Hn stencil -> MMA2(2 passes K=128) -> FC -> poly update.
// Weights loaded ONCE per CTA. Next tile's Xs prefetched via cp.async.
//
// SMEM (bytes):
//   W1   @0       128x272  (combined [W1s|W1n] K=128)
//   W2S  @34816   128x272
//   W2N  @69632   128x272
//   XA   @104448  144x272  (A of MMA1: [Xs|Xn]) --> aliased by Hs (132x272)
//   HN   @143616  128x272
//   XR   @178432  148x144  (raw sampled rows -4..131; 136..147 zero)
//   PW   @199744, B1 @201792, B2 @202304, FC @202816, PP @203840, RED @204928
//   total 209024
// ---------------------------------------------------------------------------
#define LDW 272
#define LDX 144
#define SM_W1    0
#define SM_W2S   34816
#define SM_W2N   69632
#define SM_XA    104448
#define SM_HS    104448
#define SM_HN    143616
#define SM_XR    178432
#define SM_PW    199744
#define SM_B1    201792
#define SM_B2    202304
#define SM_FC    202816
#define SM_PP    203840   /* 136*2 f32 */
#define SM_RED   204928   /* 128*8 f32 */
#define SM_TOTAL 209024

__global__ void __launch_bounds__(512, 1)
gemm12_kernel(const float* __restrict__ poly_in,
              float* __restrict__ poly_out,
              const float* __restrict__ b1_g,
              const float* __restrict__ b2_g,
              const float* __restrict__ wfc_g,
              const float* __restrict__ bfc_g,
              int step)
{
    extern __shared__ char sm[];
    uint32_t sb = smem_u32(sm);
    int tid = threadIdx.x, wid = tid >> 5, lane = tid & 31;
    int wm = wid & 3, wn = wid >> 2;
    int l7 = lane & 7, l8 = (lane >> 3) & 1, l16 = (lane >> 4) & 1;

    // ------- one-time fills: weights, scalars, XR zero-pad, tile0 prefetch ---
    {
        const uint4* w1v  = (const uint4*)(g_w1T  + (size_t)step*16384);
        const uint4* w2sv = (const uint4*)(g_w2sT + (size_t)step*16384);
        const uint4* w2nv = (const uint4*)(g_w2nT + (size_t)step*16384);
        for (int idx = tid; idx < 128*16; idx += 512) {
            int r = idx >> 4, q = idx & 15;
            *(uint4*)(sm + SM_W1  + r*LDW + q*16) = w1v[idx];
            *(uint4*)(sm + SM_W2S + r*LDW + q*16) = w2sv[idx];
            *(uint4*)(sm + SM_W2N + r*LDW + q*16) = w2nv[idx];
        }
        if (tid < 128) {
            ((float*)(sm + SM_B1))[tid] = b1_g[tid];
            ((float*)(sm + SM_B2))[tid] = b2_g[tid];
        }
        if (tid < 256) ((float*)(sm + SM_FC))[tid] = wfc_g[tid];
        ((float*)(sm + SM_PW))[tid & 511] = g_pw[step*512 + (tid & 511)];
        if (tid < 432) {                      // zero XR rows 136..147
            int r = 136 + tid/36, w = tid%36;
            *(uint32_t*)(sm + SM_XR + r*LDX + w*4) = 0;
        }
        // prefetch tile 0 Xs
        int r0 = blockIdx.x * 128;
        int n0 = r0 & (NV-1);
        int pbase = r0 - n0;
        for (int idx = tid; idx < 136*8; idx += 512) {
            int r = idx >> 3, q = idx & 7;
            int n = (n0 + r - 4 + NV) & (NV-1);
            CP_ASYNC16(sb + SM_XR + r*LDX + q*16,
                       (const char*)g_featb + ((size_t)(pbase + n)*64 + q*8)*2);
        }
        CP_COMMIT();
    }

    for (int t = 0; t < TILES_PER_CTA; t++) {
        int r0 = (t*GRID_C + blockIdx.x) * 128;
        int n0 = r0 & (NV-1);
        int pbase = r0 - n0;

        CP_WAIT0();
        __syncthreads();   // XR(t) ready; prior tile's SMEM reads complete

        // poly rows -4..131 for this tile
        if (tid < 272) {
            int rr = tid >> 1, c = tid & 1;
            int g = pbase + ((n0 + rr - 4 + NV) & (NV-1));
            ((float*)(sm + SM_PP))[tid] = poly_in[(size_t)g*2 + c];
        }

        // ---- XA build: cols 0-63 self (XR[r+2]), cols 64-127 ring stencil ----
        for (int w = tid; w < 144*64; w += 512) {
            int r = w >> 6, cw = w & 63;
            if (cw < 32) {
                *(uint32_t*)(sm + SM_XA + r*LDW + cw*4) =
                    *(uint32_t*)(sm + SM_XR + (r+2)*LDX + cw*4);
            } else {
                int j = cw - 32;
                float sx = 0.f, sy = 0.f;
                #pragma unroll
                for (int d = 0; d < 4; d++) {
                    static const int doff[4] = {0, 1, 3, 4};
                    uint32_t v = *(uint32_t*)(sm + SM_XR + (r + doff[d])*LDX + j*4);
                    float2 f = __bfloat1622float2(*(__nv_bfloat162*)&v);
                    sx += f.x; sy += f.y;
                }
                __nv_bfloat162 o = __float22bfloat162_rn(make_float2(0.25f*sx, 0.25f*sy));
                *(uint32_t*)(sm + SM_XA + r*LDW + cw*4) = *(uint32_t*)&o;
            }
        }
        __syncthreads();   // XA ready; XR now dead

        // ---- prefetch next tile's Xs into XR (overlaps MMA1/MMA2) ----
        if (t + 1 < TILES_PER_CTA) {
            int r0n = ((t+1)*GRID_C + blockIdx.x) * 128;
            int n0n = r0n & (NV-1);
            int pbn = r0n - n0n;
            for (int idx = tid; idx < 136*8; idx += 512) {
                int r = idx >> 3, q = idx & 7;
                int n = (n0n + r - 4 + NV) & (NV-1);
                CP_ASYNC16(sb + SM_XR + r*LDX + q*16,
                           (const char*)g_featb + ((size_t)(pbn + n)*64 + q*8)*2);
            }
            CP_COMMIT();
        }

        // ---- MMA1: single pass K=128, rows 0..143 (h1 rows -2..129 + pad) ----
        float acc1[2][4][4];
        float accH[4][4];
        #pragma unroll
        for (int mf = 0; mf < 2; mf++)
            #pragma unroll
            for (int nf = 0; nf < 4; nf++)
                #pragma unroll
                for (int j = 0; j < 4; j++) { acc1[mf][nf][j] = 0.f; if (mf==0) accH[nf][j] = 0.f; }

        #pragma unroll
        for (int kt = 0; kt < 8; kt++) {
            uint32_t a[2][4], ah[4];
            #pragma unroll
            for (int mf = 0; mf < 2; mf++)
                ldmx4(a[mf], sb + SM_XA + (wm*32 + mf*16 + l7 + l8*8)*LDW + l16*16 + kt*32);
            if (wm == 0)
                ldmx4(ah, sb + SM_XA + (128 + l7 + l8*8)*LDW + l16*16 + kt*32);
            #pragma unroll
            for (int nf2 = 0; nf2 < 2; nf2++) {
                uint32_t b[4];
                ldmx4(b, sb + SM_W1 + (wn*32 + nf2*16 + l16*8 + l7)*LDW + kt*32 + l8*16);
                #pragma unroll
                for (int mf = 0; mf < 2; mf++) {
                    mma16816(acc1[mf][2*nf2],   a[mf], b[0], b[1]);
                    mma16816(acc1[mf][2*nf2+1], a[mf], b[2], b[3]);
                }
                if (wm == 0) {
                    mma16816(accH[2*nf2],   ah, b[0], b[1]);
                    mma16816(accH[2*nf2+1], ah, b[2], b[3]);
                }
            }
        }
        __syncthreads();   // XA reads done -> overwrite with Hs

        // ---- epilogue1 -> Hs (bf16, rows 0..131) ----
        {
            const float* PP = (const float*)(sm + SM_PP);
            const float* B  = (const float*)(sm + SM_B1);
            const float* PW = (const float*)(sm + SM_PW);
            int rlo = lane >> 2, qc = (lane & 3)*2;
            #pragma unroll
            for (int mf = 0; mf < 3; mf++) {
                if (mf == 2 && wm != 0) break;
                int hr = (mf == 2) ? (128 + rlo) : (wm*32 + mf*16 + rlo);
                bool v0 = (mf < 2) || (rlo < 4);
                bool v1 = (mf < 2);
                const float (*A0)[4] = (mf == 2) ? accH : acc1[mf];
                float px0=0,py0=0,ax0=0,ay0=0,px1=0,py1=0,ax1=0,ay1=0;
                if (v0) {
                    px0 = PP[(hr+2)*2]; py0 = PP[(hr+2)*2+1];
                    ax0 = 0.25f*(PP[hr*2]   + PP[(hr+1)*2]   + PP[(hr+3)*2]   + PP[(hr+4)*2]);
                    ay0 = 0.25f*(PP[hr*2+1] + PP[(hr+1)*2+1] + PP[(hr+3)*2+1] + PP[(hr+4)*2+1]);
                }
                int r1 = hr + 8;
                if (v1) {
                    px1 = PP[(r1+2)*2]; py1 = PP[(r1+2)*2+1];
                    ax1 = 0.25f*(PP[r1*2]   + PP[(r1+1)*2]   + PP[(r1+3)*2]   + PP[(r1+4)*2]);
                    ay1 = 0.25f*(PP[r1*2+1] + PP[(r1+1)*2+1] + PP[(r1+3)*2+1] + PP[(r1+4)*2+1]);
                }
                #pragma unroll
                for (int nf = 0; nf < 4; nf++) {
                    int n = wn*32 + nf*8 + qc;
                    float b0 = B[n],   w0x = PW[n],   w0y = PW[128+n],   w0ax = PW[256+n],   w0ay = PW[384+n];
                    float b1 = B[n+1], w1x = PW[n+1], w1y = PW[128+n+1], w1ax = PW[256+n+1], w1ay = PW[384+n+1];
                    if (v0) {
                        float v00 = A0[nf][0] + b0 + px0*w0x + py0*w0y + ax0*w0ax + ay0*w0ay;
                        float v01 = A0[nf][1] + b1 + px0*w1x + py0*w1y + ax0*w1ax + ay0*w1ay;
                        __nv_bfloat162 h0 = __float22bfloat162_rn(make_float2(fmaxf(v00,0.f), fmaxf(v01,0.f)));
                        *(uint32_t*)(sm + SM_HS + hr*LDW + n*2) = *(uint32_t*)&h0;
                    }
                    if (v1) {
                        float v10 = A0[nf][2] + b0 + px1*w0x + py1*w0y + ax1*w0ax + ay1*w0ay;
                        float v11 = A0[nf][3] + b1 + px1*w1x + py1*w1y + ax1*w1ax + ay1*w1ay;
                        __nv_bfloat162 h1 = __float22bfloat162_rn(make_float2(fmaxf(v10,0.f), fmaxf(v11,0.f)));
                        *(uint32_t*)(sm + SM_HS + r1*LDW + n*2) = *(uint32_t*)&h1;
                    }
                }
            }
        }
        __syncthreads();

        // ---- Hn ring stencil (rows 0..127) ----
        for (int w = tid; w < 128*64; w += 512) {
            int r = w >> 6, cw = w & 63;
            float sx = 0.f, sy = 0.f;
            #pragma unroll
            for (int d = 0; d < 4; d++) {
                static const int doff[4] = {0, 1, 3, 4};
                uint32_t v = *(uint32_t*)(sm + SM_HS + (r + doff[d])*LDW + cw*4);
                float2 f = __bfloat1622float2(*(__nv_bfloat162*)&v);
                sx += f.x; sy += f.y;
            }
            __nv_bfloat162 o = __float22bfloat162_rn(make_float2(0.25f*sx, 0.25f*sy));
            *(uint32_t*)(sm + SM_HN + r*LDW + cw*4) = *(uint32_t*)&o;
        }
        __syncthreads();

        // ---- MMA2: 2 passes K=128 ----
        float acc2[2][4][4];
        #pragma unroll
        for (int mf = 0; mf < 2; mf++)
            #pragma unroll
            for (int nf = 0; nf < 4; nf++)
                #pragma unroll
                for (int j = 0; j < 4; j++) acc2[mf][nf][j] = 0.f;

        #pragma unroll
        for (int pass = 0; pass < 2; pass++) {
            uint32_t xbase = sb + (pass ? SM_HN : (SM_HS + 2*LDW));
            uint32_t wbase = sb + (pass ? SM_W2N : SM_W2S);
            #pragma unroll
            for (int kt = 0; kt < 8; kt++) {
                uint32_t a[2][4];
                #pragma unroll
                for (int mf = 0; mf < 2; mf++)
                    ldmx4(a[mf], xbase + (wm*32 + mf*16 + l7 + l8*8)*LDW + l16*16 + kt*32);
                #pragma unroll
                for (int nf2 = 0; nf2 < 2; nf2++) {
                    uint32_t b[4];
                    ldmx4(b, wbase + (wn*32 + nf2*16 + l16*8 + l7)*LDW + kt*32 + l8*16);
                    #pragma unroll
                    for (int mf = 0; mf < 2; mf++) {
                        mma16816(acc2[mf][2*nf2],   a[mf], b[0], b[1]);
                        mma16816(acc2[mf][2*nf2+1], a[mf], b[2], b[3]);
                    }
                }
            }
        }

        // ---- relu + FC(128->2) + poly update ----
        {
            const float* B  = (const float*)(sm + SM_B2);
            const float* FC = (const float*)(sm + SM_FC);
            int rlo = lane >> 2, qc = (lane & 3)*2;
            float pr[2][2][2];
            #pragma unroll
            for (int mf = 0; mf < 2; mf++)
                #pragma unroll
                for (int rh = 0; rh < 2; rh++) { pr[mf][rh][0] = 0.f; pr[mf][rh][1] = 0.f; }
            #pragma unroll
            for (int mf = 0; mf < 2; mf++)
                #pragma unroll
                for (int nf = 0; nf < 4; nf++) {
                    int n = wn*32 + nf*8 + qc;
                    float b0 = B[n], b1 = B[n+1];
                    float h00 = fmaxf(acc2[mf][nf][0] + b0, 0.f);
                    float h01 = fmaxf(acc2[mf][nf][1] + b1, 0.f);
                    float h10 = fmaxf(acc2[mf][nf][2] + b0, 0.f);
                    float h11 = fmaxf(acc2[mf][nf][3] + b1, 0.f);
                    float f0x = FC[n*2], f0y = FC[n*2+1], f1x = FC[(n+1)*2], f1y = FC[(n+1)*2+1];
                    pr[mf][0][0] += h00*f0x + h01*f1x;  pr[mf][0][1] += h00*f0y + h01*f1y;
                    pr[mf][1][0] += h10*f0x + h11*f1x;  pr[mf][1][1] += h10*f0y + h11*f1y;
                }
            #pragma unroll
            for (int mf = 0; mf < 2; mf++)
                #pragma unroll
                for (int rh = 0; rh < 2; rh++)
                    #pragma unroll
                    for (int j = 0; j < 2; j++) {
                        pr[mf][rh][j] += __shfl_xor_sync(0xffffffffu, pr[mf][rh][j], 1);
                        pr[mf][rh][j] += __shfl_xor_sync(0xffffffffu, pr[mf][rh][j], 2);
                    }
            float* RED = (float*)(sm + SM_RED);
            if ((lane & 3) == 0) {
                #pragma unroll
                for (int mf = 0; mf < 2; mf++)
                    #pragma unroll
                    for (int rh = 0; rh < 2; rh++) {
                        int row = wm*32 + mf*16 + rh*8 + rlo;
                        RED[row*8 + wn*2 + 0] = pr[mf][rh][0];
                        RED[row*8 + wn*2 + 1] = pr[mf][rh][1];
                    }
            }
            __syncthreads();
            if (tid < 256) {
                int row = tid >> 1, j = tid & 1;
                float s = RED[row*8 + j] + RED[row*8 + 2 + j]
                        + RED[row*8 + 4 + j] + RED[row*8 + 6 + j] + bfc_g[j];
                poly_out[(size_t)(r0 + row)*2 + j] =
                    ((const float*)(sm + SM_PP))[(row + 4)*2 + j] + s;
            }
        }
    }
}

// ---------------------------------------------------------------------------
extern "C" void kernel_launch(void* const* d_in, const int* in_sizes, int n_in,
                              void* d_out, int out_size)
{
    const float* feature    = (const float*)d_in[0];
    const float* init_polys = (const float*)d_in[1];
    /* d_in[2] = adj (fixed ring graph -> stencil) */
    const float* W1s = (const float*)d_in[3];
    const float* W1n = (const float*)d_in[4];
    const float* b1  = (const float*)d_in[5];
    const float* W2s = (const float*)d_in[6];
    const float* W2n = (const float*)d_in[7];
    const float* b2  = (const float*)d_in[8];
    const float* Wfc = (const float*)d_in[9];
    const float* bfc = (const float*)d_in[10];

    cudaFuncSetAttribute(gemm12_kernel, cudaFuncAttributeMaxDynamicSharedMemorySize, SM_TOTAL);

    float *polyA, *polyB;
    cudaGetSymbolAddress((void**)&polyA, g_polyA);
    cudaGetSymbolAddress((void**)&polyB, g_polyB);

    prep_kernel<<<3, 256>>>(W1s, W1n, W2s, W2n);

    float* pouts[3] = { polyA, polyB, (float*)d_out };
    const float* pin = init_polys;
    for (int i = 0; i < 3; i++) {
        sample_kernel<<<M/16, dim3(16,16)>>>(feature, pin, i);
        gemm12_kernel<<<GRID_C, 512, SM_TOTAL>>>(pin, pouts[i],
                                                 b1 + i*S, b2 + i*S,
                                                 Wfc + i*S*2, bfc + i*2, i);
        pin = pouts[i];
    }
}

// round 9
// speedup vs baseline: 1.4774x; 1.1470x over previous
#include <cuda_runtime.h>
#include <cuda_bf16.h>
#include <cstdint>

#define GRID_W 112
#define HW (GRID_W*GRID_W)
#define NV 512
#define NP 128
#define M (NP*NV)        /* 65536 rows */
#define S 128
#define GRID_C 128       /* persistent CTAs */
#define TILES_PER_CTA 4

// ---------------------------------------------------------------------------
// PTX helpers (sm_80+ : valid for compute_103)
// ---------------------------------------------------------------------------
__device__ __forceinline__ uint32_t smem_u32(const void* p) {
    uint32_t a;
    asm("{ .reg .u64 t; cvta.to.shared.u64 t, %1; cvt.u32.u64 %0, t; }" : "=r"(a) : "l"(p));
    return a;
}
__device__ __forceinline__ void ldmx4(uint32_t* r, uint32_t addr) {
    asm volatile("ldmatrix.sync.aligned.m8n8.x4.shared.b16 {%0,%1,%2,%3}, [%4];"
        : "=r"(r[0]), "=r"(r[1]), "=r"(r[2]), "=r"(r[3]) : "r"(addr));
}
__device__ __forceinline__ void mma16816(float* d, const uint32_t* a,
                                         uint32_t b0, uint32_t b1) {
    asm volatile(
        "mma.sync.aligned.m16n8k16.row.col.f32.bf16.bf16.f32 "
        "{%0,%1,%2,%3}, {%4,%5,%6,%7}, {%8,%9}, {%0,%1,%2,%3};"
        : "+f"(d[0]), "+f"(d[1]), "+f"(d[2]), "+f"(d[3])
        : "r"(a[0]), "r"(a[1]), "r"(a[2]), "r"(a[3]), "r"(b0), "r"(b1));
}
#define CP_ASYNC16(dst, src) \
    asm volatile("cp.async.cg.shared.global [%0], [%1], 16;" :: "r"(dst), "l"(src))
#define CP_COMMIT() asm volatile("cp.async.commit_group;")
#define CP_WAIT0()  asm volatile("cp.async.wait_group 0;")

// 4-tap ring average on 4 bf16 lanes (one uint2) : 0.25*(a+b+c+d)
__device__ __forceinline__ uint2 ring4_bf16x4(uint2 a, uint2 b, uint2 c, uint2 d) {
    const __nv_bfloat162 q = __float2bfloat162_rn(0.25f);
    __nv_bfloat162 s0 = __hmul2(q, __hadd2(__hadd2(*(__nv_bfloat162*)&a.x, *(__nv_bfloat162*)&b.x),
                                           __hadd2(*(__nv_bfloat162*)&c.x, *(__nv_bfloat162*)&d.x)));
    __nv_bfloat162 s1 = __hmul2(q, __hadd2(__hadd2(*(__nv_bfloat162*)&a.y, *(__nv_bfloat162*)&b.y),
                                           __hadd2(*(__nv_bfloat162*)&c.y, *(__nv_bfloat162*)&d.y)));
    return make_uint2(*(uint32_t*)&s0, *(uint32_t*)&s1);
}

// ---------------------------------------------------------------------------
// Scratch globals
// ---------------------------------------------------------------------------
__device__ __align__(16) __nv_bfloat16 g_featb[(size_t)M*64];   // sampled features
__device__ float g_polyA[(size_t)M*2];
__device__ float g_polyB[(size_t)M*2];
__device__ __align__(16) __nv_bfloat16 g_w1T[3*128*128];   // [step][n][k] k<64:W1s, k>=64:W1n
__device__ __align__(16) __nv_bfloat16 g_w2sT[3*128*128];
__device__ __align__(16) __nv_bfloat16 g_w2nT[3*128*128];
__device__ float g_pw[3*4*128];  // poly-weight rows: Ws[64],Ws[65],Wn[64],Wn[65]

// ---------------------------------------------------------------------------
// Prep: transpose + bf16-convert weights (once per launch; grid=3 steps)
// ---------------------------------------------------------------------------
__global__ void prep_kernel(const float* __restrict__ W1s, const float* __restrict__ W1n,
                            const float* __restrict__ W2s, const float* __restrict__ W2n)
{
    int i = blockIdx.x;
    int tid = threadIdx.x;
    const float* w1s = W1s + (size_t)i*66*128;
    const float* w1n = W1n + (size_t)i*66*128;
    for (int idx = tid; idx < 128*128; idx += 256) {
        int n = idx >> 7, k = idx & 127;
        float v = (k < 64) ? w1s[k*128 + n] : w1n[(k-64)*128 + n];
        g_w1T[(size_t)i*16384 + idx] = __float2bfloat16(v);
    }
    if (tid < 128) {
        g_pw[i*512 +       tid] = w1s[64*128 + tid];
        g_pw[i*512 + 128 + tid] = w1s[65*128 + tid];
        g_pw[i*512 + 256 + tid] = w1n[64*128 + tid];
        g_pw[i*512 + 384 + tid] = w1n[65*128 + tid];
    }
    const float* w2s = W2s + (size_t)i*128*128;
    const float* w2n = W2n + (size_t)i*128*128;
    for (int idx = tid; idx < 128*128; idx += 256) {
        int n = idx >> 7, k = idx & 127;
        g_w2sT[(size_t)i*16384 + idx] = __float2bfloat16(w2s[k*128 + n]);
        g_w2nT[(size_t)i*16384 + idx] = __float2bfloat16(w2n[k*128 + n]);
    }
}

// ---------------------------------------------------------------------------
// Sampler: gather features at poly coords -> g_featb [M,64] bf16
// ---------------------------------------------------------------------------
__global__ void sample_kernel(const float* __restrict__ feature,
                              const float* __restrict__ poly, int step)
{
    int v  = blockIdx.x * 16 + threadIdx.y;
    int c4 = threadIdx.x;               // 0..15 (4 floats each)
    int p  = v >> 9;
    float px = poly[v*2+0];
    float py = poly[v*2+1];
    const float4* fb = (const float4*)(feature + (size_t)p * HW * 64);
    float4 val;
    if (step == 0) {
        int xi = (int)fminf(fmaxf(floorf(px*GRID_W), 0.f), 111.f);
        int yi = (int)fminf(fmaxf(floorf(py*GRID_W), 0.f), 111.f);
        val = fb[(size_t)(xi + yi*GRID_W)*16 + c4];
    } else {
        float Xs = px*GRID_W, Ys = py*GRID_W;
        float X0 = floorf(Xs), Y0 = floorf(Ys);
        float wx = Xs - X0, wy = Ys - Y0;
        int x0 = (int)fminf(fmaxf(X0,     0.f), 111.f);
        int x1 = (int)fminf(fmaxf(X0+1.f, 0.f), 111.f);
        int y0 = (int)fminf(fmaxf(Y0,     0.f), 111.f);
        int y1 = (int)fminf(fmaxf(Y0+1.f, 0.f), 111.f);
        float4 m00 = fb[(size_t)(x0 + y0*GRID_W)*16 + c4];
        float4 m01 = fb[(size_t)(x0 + y1*GRID_W)*16 + c4];
        float4 m10 = fb[(size_t)(x1 + y0*GRID_W)*16 + c4];
        float4 m11 = fb[(size_t)(x1 + y1*GRID_W)*16 + c4];
        float w00 = (1.f-wx)*(1.f-wy), w01 = (1.f-wx)*wy;
        float w10 = wx*(1.f-wy),       w11 = wx*wy;
        val.x = w00*m00.x + w01*m01.x + w10*m10.x + w11*m11.x;
        val.y = w00*m00.y + w01*m01.y + w10*m10.y + w11*m11.y;
        val.z = w00*m00.z + w01*m01.z + w10*m10.z + w11*m11.z;
        val.w = w00*m00.w + w01*m01.w + w10*m10.w + w11*m11.w;
    }
    __nv_bfloat162 o0 = __float22bfloat162_rn(make_float2(val.x, val.y));
    __nv_bfloat162 o1 = __float22bfloat162_rn(make_float2(val.z, val.w));
    *(uint2*)(g_featb + (size_t)v*64 + c4*4) =
        make_uint2(*(uint32_t*)&o0, *(uint32_t*)&o1);
}

// ---------------------------------------------------------------------------
// Persistent fused GEMM kernel. 128 CTAs x 4 tiles, 512 thr, 16 warps (4m x 4n).
// SMEM layout identical to R8 (see offsets).
// ---------------------------------------------------------------------------
#define LDW 272
#define LDX 144
#define SM_W1    0
#define SM_W2S   34816
#define SM_W2N   69632
#define SM_XA    104448
#define SM_HS    104448
#define SM_HN    143616
#define SM_XR    178432
#define SM_PW    199744
#define SM_B1    201792
#define SM_B2    202304
#define SM_FC    202816
#define SM_PP    203840   /* 136*2 f32 */
#define SM_RED   204928   /* 128*8 f32 */
#define SM_TOTAL 209024

__global__ void __launch_bounds__(512, 1)
gemm12_kernel(const float* __restrict__ poly_in,
              float* __restrict__ poly_out,
              const float* __restrict__ b1_g,
              const float* __restrict__ b2_g,
              const float* __restrict__ wfc_g,
              const float* __restrict__ bfc_g,
              int step)
{
    extern __shared__ char sm[];
    uint32_t sb = smem_u32(sm);
    int tid = threadIdx.x, wid = tid >> 5, lane = tid & 31;
    int wm = wid & 3, wn = wid >> 2;
    int l7 = lane & 7, l8 = (lane >> 3) & 1, l16 = (lane >> 4) & 1;

    // ------- one-time fills: weights, scalars, XR zero-pad, tile0 prefetch ---
    {
        const uint4* w1v  = (const uint4*)(g_w1T  + (size_t)step*16384);
        const uint4* w2sv = (const uint4*)(g_w2sT + (size_t)step*16384);
        const uint4* w2nv = (const uint4*)(g_w2nT + (size_t)step*16384);
        for (int idx = tid; idx < 128*16; idx += 512) {
            int r = idx >> 4, q = idx & 15;
            *(uint4*)(sm + SM_W1  + r*LDW + q*16) = w1v[idx];
            *(uint4*)(sm + SM_W2S + r*LDW + q*16) = w2sv[idx];
            *(uint4*)(sm + SM_W2N + r*LDW + q*16) = w2nv[idx];
        }
        if (tid < 128) {
            ((float*)(sm + SM_B1))[tid] = b1_g[tid];
            ((float*)(sm + SM_B2))[tid] = b2_g[tid];
        }
        if (tid < 256) ((float*)(sm + SM_FC))[tid] = wfc_g[tid];
        ((float*)(sm + SM_PW))[tid & 511] = g_pw[step*512 + (tid & 511)];
        if (tid < 432) {                      // zero XR rows 136..147
            int r = 136 + tid/36, w = tid%36;
            *(uint32_t*)(sm + SM_XR + r*LDX + w*4) = 0;
        }
        // prefetch tile 0 Xs
        int r0 = blockIdx.x * 128;
        int n0 = r0 & (NV-1);
        int pbase = r0 - n0;
        for (int idx = tid; idx < 136*8; idx += 512) {
            int r = idx >> 3, q = idx & 7;
            int n = (n0 + r - 4 + NV) & (NV-1);
            CP_ASYNC16(sb + SM_XR + r*LDX + q*16,
                       (const char*)g_featb + ((size_t)(pbase + n)*64 + q*8)*2);
        }
        CP_COMMIT();
    }

    for (int t = 0; t < TILES_PER_CTA; t++) {
        int r0 = (t*GRID_C + blockIdx.x) * 128;
        int n0 = r0 & (NV-1);
        int pbase = r0 - n0;

        CP_WAIT0();
        __syncthreads();   // XR(t) ready; prior tile's SMEM reads complete

        // poly rows -4..131 for this tile
        if (tid < 272) {
            int rr = tid >> 1, c = tid & 1;
            int g = pbase + ((n0 + rr - 4 + NV) & (NV-1));
            ((float*)(sm + SM_PP))[tid] = poly_in[(size_t)g*2 + c];
        }

        // ---- XA build: uint4 self-copy + bf16x2 SIMD ring stencil ----
        // self half: XA[r][words 0..31] = XR[r+2][words 0..31]  (8 uint4/row)
        for (int w = tid; w < 144*8; w += 512) {
            int r = w >> 3, q = w & 7;
            *(uint4*)(sm + SM_XA + r*LDW + q*16) = *(uint4*)(sm + SM_XR + (r+2)*LDX + q*16);
        }
        // ring half: XA[r][words 32..63] = 0.25*(XR[r]+XR[r+1]+XR[r+3]+XR[r+4]) (uint2 grain)
        for (int w = tid; w < 144*16; w += 512) {
            int r = w >> 4, j = w & 15;     // j = uint2 index (4 bf16)
            uint2 a = *(uint2*)(sm + SM_XR + (r  )*LDX + j*8);
            uint2 b = *(uint2*)(sm + SM_XR + (r+1)*LDX + j*8);
            uint2 c = *(uint2*)(sm + SM_XR + (r+3)*LDX + j*8);
            uint2 d = *(uint2*)(sm + SM_XR + (r+4)*LDX + j*8);
            *(uint2*)(sm + SM_XA + r*LDW + 128 + j*8) = ring4_bf16x4(a, b, c, d);
        }
        __syncthreads();   // XA ready; XR now dead

        // ---- prefetch next tile's Xs into XR (overlaps MMA1/MMA2) ----
        if (t + 1 < TILES_PER_CTA) {
            int r0n = ((t+1)*GRID_C + blockIdx.x) * 128;
            int n0n = r0n & (NV-1);
            int pbn = r0n - n0n;
            for (int idx = tid; idx < 136*8; idx += 512) {
                int r = idx >> 3, q = idx & 7;
                int n = (n0n + r - 4 + NV) & (NV-1);
                CP_ASYNC16(sb + SM_XR + r*LDX + q*16,
                           (const char*)g_featb + ((size_t)(pbn + n)*64 + q*8)*2);
            }
            CP_COMMIT();
        }

        // ---- MMA1: single pass K=128, rows 0..143 (h1 rows -2..129 + pad) ----
        float acc1[2][4][4];
        float accH[4][4];
        #pragma unroll
        for (int mf = 0; mf < 2; mf++)
            #pragma unroll
            for (int nf = 0; nf < 4; nf++)
                #pragma unroll
                for (int j = 0; j < 4; j++) { acc1[mf][nf][j] = 0.f; if (mf==0) accH[nf][j] = 0.f; }

        #pragma unroll
        for (int kt = 0; kt < 8; kt++) {
            uint32_t a[2][4], ah[4];
            #pragma unroll
            for (int mf = 0; mf < 2; mf++)
                ldmx4(a[mf], sb + SM_XA + (wm*32 + mf*16 + l7 + l8*8)*LDW + l16*16 + kt*32);
            if (wm == 0)
                ldmx4(ah, sb + SM_XA + (128 + l7 + l8*8)*LDW + l16*16 + kt*32);
            #pragma unroll
            for (int nf2 = 0; nf2 < 2; nf2++) {
                uint32_t b[4];
                ldmx4(b, sb + SM_W1 + (wn*32 + nf2*16 + l16*8 + l7)*LDW + kt*32 + l8*16);
                #pragma unroll
                for (int mf = 0; mf < 2; mf++) {
                    mma16816(acc1[mf][2*nf2],   a[mf], b[0], b[1]);
                    mma16816(acc1[mf][2*nf2+1], a[mf], b[2], b[3]);
                }
                if (wm == 0) {
                    mma16816(accH[2*nf2],   ah, b[0], b[1]);
                    mma16816(accH[2*nf2+1], ah, b[2], b[3]);
                }
            }
        }
        __syncthreads();   // XA reads done -> overwrite with Hs

        // ---- epilogue1 -> Hs (bf16, rows 0..131) ----
        {
            const float* PP = (const float*)(sm + SM_PP);
            const float* B  = (const float*)(sm + SM_B1);
            const float* PW = (const float*)(sm + SM_PW);
            int rlo = lane >> 2, qc = (lane & 3)*2;
            #pragma unroll
            for (int mf = 0; mf < 3; mf++) {
                if (mf == 2 && wm != 0) break;
                int hr = (mf == 2) ? (128 + rlo) : (wm*32 + mf*16 + rlo);
                bool v0 = (mf < 2) || (rlo < 4);
                bool v1 = (mf < 2);
                const float (*A0)[4] = (mf == 2) ? accH : acc1[mf];
                float px0=0,py0=0,ax0=0,ay0=0,px1=0,py1=0,ax1=0,ay1=0;
                if (v0) {
                    px0 = PP[(hr+2)*2]; py0 = PP[(hr+2)*2+1];
                    ax0 = 0.25f*(PP[hr*2]   + PP[(hr+1)*2]   + PP[(hr+3)*2]   + PP[(hr+4)*2]);
                    ay0 = 0.25f*(PP[hr*2+1] + PP[(hr+1)*2+1] + PP[(hr+3)*2+1] + PP[(hr+4)*2+1]);
                }
                int r1 = hr + 8;
                if (v1) {
                    px1 = PP[(r1+2)*2]; py1 = PP[(r1+2)*2+1];
                    ax1 = 0.25f*(PP[r1*2]   + PP[(r1+1)*2]   + PP[(r1+3)*2]   + PP[(r1+4)*2]);
                    ay1 = 0.25f*(PP[r1*2+1] + PP[(r1+1)*2+1] + PP[(r1+3)*2+1] + PP[(r1+4)*2+1]);
                }
                #pragma unroll
                for (int nf = 0; nf < 4; nf++) {
                    int n = wn*32 + nf*8 + qc;
                    float b0 = B[n],   w0x = PW[n],   w0y = PW[128+n],   w0ax = PW[256+n],   w0ay = PW[384+n];
                    float b1 = B[n+1], w1x = PW[n+1], w1y = PW[128+n+1], w1ax = PW[256+n+1], w1ay = PW[384+n+1];
                    if (v0) {
                        float v00 = A0[nf][0] + b0 + px0*w0x + py0*w0y + ax0*w0ax + ay0*w0ay;
                        float v01 = A0[nf][1] + b1 + px0*w1x + py0*w1y + ax0*w1ax + ay0*w1ay;
                        __nv_bfloat162 h0 = __float22bfloat162_rn(make_float2(fmaxf(v00,0.f), fmaxf(v01,0.f)));
                        *(uint32_t*)(sm + SM_HS + hr*LDW + n*2) = *(uint32_t*)&h0;
                    }
                    if (v1) {
                        float v10 = A0[nf][2] + b0 + px1*w0x + py1*w0y + ax1*w0ax + ay1*w0ay;
                        float v11 = A0[nf][3] + b1 + px1*w1x + py1*w1y + ax1*w1ax + ay1*w1ay;
                        __nv_bfloat162 h1 = __float22bfloat162_rn(make_float2(fmaxf(v10,0.f), fmaxf(v11,0.f)));
                        *(uint32_t*)(sm + SM_HS + r1*LDW + n*2) = *(uint32_t*)&h1;
                    }
                }
            }
        }
        __syncthreads();

        // ---- Hn ring stencil (rows 0..127), bf16x2 SIMD, uint2 grain ----
        for (int w = tid; w < 128*32; w += 512) {
            int r = w >> 5, j = w & 31;     // j = uint2 index (4 bf16), 32 per row
            uint2 a = *(uint2*)(sm + SM_HS + (r  )*LDW + j*8);
            uint2 b = *(uint2*)(sm + SM_HS + (r+1)*LDW + j*8);
            uint2 c = *(uint2*)(sm + SM_HS + (r+3)*LDW + j*8);
            uint2 d = *(uint2*)(sm + SM_HS + (r+4)*LDW + j*8);
            *(uint2*)(sm + SM_HN + r*LDW + j*8) = ring4_bf16x4(a, b, c, d);
        }
        __syncthreads();

        // ---- MMA2: merged single loop (self + neighbor interleaved) ----
        float acc2[2][4][4];
        #pragma unroll
        for (int mf = 0; mf < 2; mf++)
            #pragma unroll
            for (int nf = 0; nf < 4; nf++)
                #pragma unroll
                for (int j = 0; j < 4; j++) acc2[mf][nf][j] = 0.f;

        #pragma unroll
        for (int kt = 0; kt < 8; kt++) {
            uint32_t as[2][4], an[2][4];
            #pragma unroll
            for (int mf = 0; mf < 2; mf++) {
                ldmx4(as[mf], sb + SM_HS + (2 + wm*32 + mf*16 + l7 + l8*8)*LDW + l16*16 + kt*32);
                ldmx4(an[mf], sb + SM_HN + (    wm*32 + mf*16 + l7 + l8*8)*LDW + l16*16 + kt*32);
            }
            #pragma unroll
            for (int nf2 = 0; nf2 < 2; nf2++) {
                uint32_t bs[4], bn[4];
                ldmx4(bs, sb + SM_W2S + (wn*32 + nf2*16 + l16*8 + l7)*LDW + kt*32 + l8*16);
                ldmx4(bn, sb + SM_W2N + (wn*32 + nf2*16 + l16*8 + l7)*LDW + kt*32 + l8*16);
                #pragma unroll
                for (int mf = 0; mf < 2; mf++) {
                    mma16816(acc2[mf][2*nf2],   as[mf], bs[0], bs[1]);
                    mma16816(acc2[mf][2*nf2+1], as[mf], bs[2], bs[3]);
                    mma16816(acc2[mf][2*nf2],   an[mf], bn[0], bn[1]);
                    mma16816(acc2[mf][2*nf2+1], an[mf], bn[2], bn[3]);
                }
            }
        }

        // ---- relu + FC(128->2) + poly update ----
        {
            const float* B  = (const float*)(sm + SM_B2);
            const float* FC = (const float*)(sm + SM_FC);
            int rlo = lane >> 2, qc = (lane & 3)*2;
            float pr[2][2][2];
            #pragma unroll
            for (int mf = 0; mf < 2; mf++)
                #pragma unroll
                for (int rh = 0; rh < 2; rh++) { pr[mf][rh][0] = 0.f; pr[mf][rh][1] = 0.f; }
            #pragma unroll
            for (int mf = 0; mf < 2; mf++)
                #pragma unroll
                for (int nf = 0; nf < 4; nf++) {
                    int n = wn*32 + nf*8 + qc;
                    float b0 = B[n], b1 = B[n+1];
                    float h00 = fmaxf(acc2[mf][nf][0] + b0, 0.f);
                    float h01 = fmaxf(acc2[mf][nf][1] + b1, 0.f);
                    float h10 = fmaxf(acc2[mf][nf][2] + b0, 0.f);
                    float h11 = fmaxf(acc2[mf][nf][3] + b1, 0.f);
                    float f0x = FC[n*2], f0y = FC[n*2+1], f1x = FC[(n+1)*2], f1y = FC[(n+1)*2+1];
                    pr[mf][0][0] += h00*f0x + h01*f1x;  pr[mf][0][1] += h00*f0y + h01*f1y;
                    pr[mf][1][0] += h10*f0x + h11*f1x;  pr[mf][1][1] += h10*f0y + h11*f1y;
                }
            #pragma unroll
            for (int mf = 0; mf < 2; mf++)
                #pragma unroll
                for (int rh = 0; rh < 2; rh++)
                    #pragma unroll
                    for (int j = 0; j < 2; j++) {
                        pr[mf][rh][j] += __shfl_xor_sync(0xffffffffu, pr[mf][rh][j], 1);
                        pr[mf][rh][j] += __shfl_xor_sync(0xffffffffu, pr[mf][rh][j], 2);
                    }
            float* RED = (float*)(sm + SM_RED);
            if ((lane & 3) == 0) {
                #pragma unroll
                for (int mf = 0; mf < 2; mf++)
                    #pragma unroll
                    for (int rh = 0; rh < 2; rh++) {
                        int row = wm*32 + mf*16 + rh*8 + rlo;
                        RED[row*8 + wn*2 + 0] = pr[mf][rh][0];
                        RED[row*8 + wn*2 + 1] = pr[mf][rh][1];
                    }
            }
            __syncthreads();
            if (tid < 256) {
                int row = tid >> 1, j = tid & 1;
                float s = RED[row*8 + j] + RED[row*8 + 2 + j]
                        + RED[row*8 + 4 + j] + RED[row*8 + 6 + j] + bfc_g[j];
                poly_out[(size_t)(r0 + row)*2 + j] =
                    ((const float*)(sm + SM_PP))[(row + 4)*2 + j] + s;
            }
        }
    }
}

// ---------------------------------------------------------------------------
extern "C" void kernel_launch(void* const* d_in, const int* in_sizes, int n_in,
                              void* d_out, int out_size)
{
    const float* feature    = (const float*)d_in[0];
    const float* init_polys = (const float*)d_in[1];
    /* d_in[2] = adj (fixed ring graph -> stencil) */
    const float* W1s = (const float*)d_in[3];
    const float* W1n = (const float*)d_in[4];
    const float* b1  = (const float*)d_in[5];
    const float* W2s = (const float*)d_in[6];
    const float* W2n = (const float*)d_in[7];
    const float* b2  = (const float*)d_in[8];
    const float* Wfc = (const float*)d_in[9];
    const float* bfc = (const float*)d_in[10];

    cudaFuncSetAttribute(gemm12_kernel, cudaFuncAttributeMaxDynamicSharedMemorySize, SM_TOTAL);

    float *polyA, *polyB;
    cudaGetSymbolAddress((void**)&polyA, g_polyA);
    cudaGetSymbolAddress((void**)&polyB, g_polyB);

    prep_kernel<<<3, 256>>>(W1s, W1n, W2s, W2n);

    float* pouts[3] = { polyA, polyB, (float*)d_out };
    const float* pin = init_polys;
    for (int i = 0; i < 3; i++) {
        sample_kernel<<<M/16, dim3(16,16)>>>(feature, pin, i);
        gemm12_kernel<<<GRID_C, 512, SM_TOTAL>>>(pin, pouts[i],
                                                 b1 + i*S, b2 + i*S,
                                                 Wfc + i*S*2, bfc + i*2, i);
        pin = pouts[i];
    }
}

// round 10
// speedup vs baseline: 1.5480x; 1.0478x over previous
#include <cuda_runtime.h>
#include <cuda_bf16.h>
#include <cstdint>

#define GRID_W 112
#define HW (GRID_W*GRID_W)
#define NV 512
#define NP 128
#define M (NP*NV)        /* 65536 rows */
#define S 128
#define GRID_C 128       /* persistent CTAs */
#define TILES_PER_CTA 4

// ---------------------------------------------------------------------------
// PTX helpers (sm_80+ : valid for compute_103)
// ---------------------------------------------------------------------------
__device__ __forceinline__ uint32_t smem_u32(const void* p) {
    uint32_t a;
    asm("{ .reg .u64 t; cvta.to.shared.u64 t, %1; cvt.u32.u64 %0, t; }" : "=r"(a) : "l"(p));
    return a;
}
__device__ __forceinline__ void ldmx4(uint32_t* r, uint32_t addr) {
    asm volatile("ldmatrix.sync.aligned.m8n8.x4.shared.b16 {%0,%1,%2,%3}, [%4];"
        : "=r"(r[0]), "=r"(r[1]), "=r"(r[2]), "=r"(r[3]) : "r"(addr));
}
__device__ __forceinline__ void mma16816(float* d, const uint32_t* a,
                                         uint32_t b0, uint32_t b1) {
    asm volatile(
        "mma.sync.aligned.m16n8k16.row.col.f32.bf16.bf16.f32 "
        "{%0,%1,%2,%3}, {%4,%5,%6,%7}, {%8,%9}, {%0,%1,%2,%3};"
        : "+f"(d[0]), "+f"(d[1]), "+f"(d[2]), "+f"(d[3])
        : "r"(a[0]), "r"(a[1]), "r"(a[2]), "r"(a[3]), "r"(b0), "r"(b1));
}
#define CP_ASYNC16(dst, src) \
    asm volatile("cp.async.cg.shared.global [%0], [%1], 16;" :: "r"(dst), "l"(src))
#define CP_COMMIT() asm volatile("cp.async.commit_group;")
#define CP_WAIT0()  asm volatile("cp.async.wait_group 0;")

// 4-tap ring average on 4 bf16 lanes (one uint2) : 0.25*(a+b+c+d)
__device__ __forceinline__ uint2 ring4_bf16x4(uint2 a, uint2 b, uint2 c, uint2 d) {
    const __nv_bfloat162 q = __float2bfloat162_rn(0.25f);
    __nv_bfloat162 s0 = __hmul2(q, __hadd2(__hadd2(*(__nv_bfloat162*)&a.x, *(__nv_bfloat162*)&b.x),
                                           __hadd2(*(__nv_bfloat162*)&c.x, *(__nv_bfloat162*)&d.x)));
    __nv_bfloat162 s1 = __hmul2(q, __hadd2(__hadd2(*(__nv_bfloat162*)&a.y, *(__nv_bfloat162*)&b.y),
                                           __hadd2(*(__nv_bfloat162*)&c.y, *(__nv_bfloat162*)&d.y)));
    return make_uint2(*(uint32_t*)&s0, *(uint32_t*)&s1);
}

// ---------------------------------------------------------------------------
// Scratch globals
// ---------------------------------------------------------------------------
__device__ __align__(16) __nv_bfloat16 g_featb[(size_t)M*64];   // sampled features
__device__ float g_polyA[(size_t)M*2];
__device__ float g_polyB[(size_t)M*2];
__device__ __align__(16) __nv_bfloat16 g_w1T[3*128*128];   // [step][n][k] k<64:W1s, k>=64:W1n
__device__ __align__(16) __nv_bfloat16 g_w2sT[3*128*128];
__device__ __align__(16) __nv_bfloat16 g_w2nT[3*128*128];
__device__ float g_pw[3*4*128];  // poly-weight rows: Ws[64],Ws[65],Wn[64],Wn[65]

// ---------------------------------------------------------------------------
// Prep: transpose + bf16-convert weights (once per launch; grid=3 steps)
// ---------------------------------------------------------------------------
__global__ void prep_kernel(const float* __restrict__ W1s, const float* __restrict__ W1n,
                            const float* __restrict__ W2s, const float* __restrict__ W2n)
{
    int i = blockIdx.x;
    int tid = threadIdx.x;
    const float* w1s = W1s + (size_t)i*66*128;
    const float* w1n = W1n + (size_t)i*66*128;
    for (int idx = tid; idx < 128*128; idx += 256) {
        int n = idx >> 7, k = idx & 127;
        float v = (k < 64) ? w1s[k*128 + n] : w1n[(k-64)*128 + n];
        g_w1T[(size_t)i*16384 + idx] = __float2bfloat16(v);
    }
    if (tid < 128) {
        g_pw[i*512 +       tid] = w1s[64*128 + tid];
        g_pw[i*512 + 128 + tid] = w1s[65*128 + tid];
        g_pw[i*512 + 256 + tid] = w1n[64*128 + tid];
        g_pw[i*512 + 384 + tid] = w1n[65*128 + tid];
    }
    const float* w2s = W2s + (size_t)i*128*128;
    const float* w2n = W2n + (size_t)i*128*128;
    for (int idx = tid; idx < 128*128; idx += 256) {
        int n = idx >> 7, k = idx & 127;
        g_w2sT[(size_t)i*16384 + idx] = __float2bfloat16(w2s[k*128 + n]);
        g_w2nT[(size_t)i*16384 + idx] = __float2bfloat16(w2n[k*128 + n]);
    }
}

// ---------------------------------------------------------------------------
// Sampler: gather features at poly coords -> g_featb [M,64] bf16
// block (8,32): tx = chunk (handles c4 = tx and tx+8), ty = vertex.
// 8 independent float4 gathers in flight per thread (interp path).
// ---------------------------------------------------------------------------
__global__ void sample_kernel(const float* __restrict__ feature,
                              const float* __restrict__ poly, int step)
{
    int v  = blockIdx.x * 32 + threadIdx.y;
    int c4 = threadIdx.x;               // 0..7; chunks c4 and c4+8
    int p  = v >> 9;
    float px = poly[v*2+0];
    float py = poly[v*2+1];
    const float4* fb = (const float4*)(feature + (size_t)p * HW * 64);
    float4 val[2];
    if (step == 0) {
        int xi = (int)fminf(fmaxf(floorf(px*GRID_W), 0.f), 111.f);
        int yi = (int)fminf(fmaxf(floorf(py*GRID_W), 0.f), 111.f);
        size_t base = (size_t)(xi + yi*GRID_W)*16;
        val[0] = fb[base + c4];
        val[1] = fb[base + c4 + 8];
    } else {
        float Xs = px*GRID_W, Ys = py*GRID_W;
        float X0 = floorf(Xs), Y0 = floorf(Ys);
        float wx = Xs - X0, wy = Ys - Y0;
        int x0 = (int)fminf(fmaxf(X0,     0.f), 111.f);
        int x1 = (int)fminf(fmaxf(X0+1.f, 0.f), 111.f);
        int y0 = (int)fminf(fmaxf(Y0,     0.f), 111.f);
        int y1 = (int)fminf(fmaxf(Y0+1.f, 0.f), 111.f);
        size_t b00 = (size_t)(x0 + y0*GRID_W)*16;
        size_t b01 = (size_t)(x0 + y1*GRID_W)*16;
        size_t b10 = (size_t)(x1 + y0*GRID_W)*16;
        size_t b11 = (size_t)(x1 + y1*GRID_W)*16;
        float4 m00[2], m01[2], m10[2], m11[2];
        #pragma unroll
        for (int h = 0; h < 2; h++) {
            int cc = c4 + h*8;
            m00[h] = fb[b00 + cc];
            m01[h] = fb[b01 + cc];
            m10[h] = fb[b10 + cc];
            m11[h] = fb[b11 + cc];
        }
        float w00 = (1.f-wx)*(1.f-wy), w01 = (1.f-wx)*wy;
        float w10 = wx*(1.f-wy),       w11 = wx*wy;
        #pragma unroll
        for (int h = 0; h < 2; h++) {
            val[h].x = w00*m00[h].x + w01*m01[h].x + w10*m10[h].x + w11*m11[h].x;
            val[h].y = w00*m00[h].y + w01*m01[h].y + w10*m10[h].y + w11*m11[h].y;
            val[h].z = w00*m00[h].z + w01*m01[h].z + w10*m10[h].z + w11*m11[h].z;
            val[h].w = w00*m00[h].w + w01*m01[h].w + w10*m10[h].w + w11*m11[h].w;
        }
    }
    #pragma unroll
    for (int h = 0; h < 2; h++) {
        __nv_bfloat162 o0 = __float22bfloat162_rn(make_float2(val[h].x, val[h].y));
        __nv_bfloat162 o1 = __float22bfloat162_rn(make_float2(val[h].z, val[h].w));
        *(uint2*)(g_featb + (size_t)v*64 + (c4 + h*8)*4) =
            make_uint2(*(uint32_t*)&o0, *(uint32_t*)&o1);
    }
}

// ---------------------------------------------------------------------------
// Persistent fused GEMM kernel. 128 CTAs x 4 tiles, 512 thr, 16 warps (4m x 4n).
// No SMEM aliasing: MMA1 self-half reads XR directly; ring half from XN.
// SMEM (bytes):
//   W1 @0  W2S @34816  W2N @69632   (128 x 272 each)
//   HS @104448 (132 x 272)   HN @140352 (128 x 272)
//   XN @175168 (144 x 144)   XR @195904 (148 x 144)
//   PW @217216  B1 @219264  B2 @219776  FC @220288  PP @221312  RED @222400
// ---------------------------------------------------------------------------
#define LDW 272
#define LDX 144
#define SM_W1    0
#define SM_W2S   34816
#define SM_W2N   69632
#define SM_HS    104448
#define SM_HN    140352
#define SM_XN    175168
#define SM_XR    195904
#define SM_PW    217216
#define SM_B1    219264
#define SM_B2    219776
#define SM_FC    220288
#define SM_PP    221312   /* 136*2 f32 */
#define SM_RED   222400   /* 128*8 f32 */
#define SM_TOTAL 226496

__global__ void __launch_bounds__(512, 1)
gemm12_kernel(const float* __restrict__ poly_in,
              float* __restrict__ poly_out,
              const float* __restrict__ b1_g,
              const float* __restrict__ b2_g,
              const float* __restrict__ wfc_g,
              const float* __restrict__ bfc_g,
              int step)
{
    extern __shared__ char sm[];
    uint32_t sb = smem_u32(sm);
    int tid = threadIdx.x, wid = tid >> 5, lane = tid & 31;
    int wm = wid & 3, wn = wid >> 2;
    int l7 = lane & 7, l8 = (lane >> 3) & 1, l16 = (lane >> 4) & 1;

    // ------- prologue: cp.async weights + tile0 XR; scalars; XR zero-pad ----
    {
        const char* w1p  = (const char*)(g_w1T  + (size_t)step*16384);
        const char* w2sp = (const char*)(g_w2sT + (size_t)step*16384);
        const char* w2np = (const char*)(g_w2nT + (size_t)step*16384);
        for (int idx = tid; idx < 128*16; idx += 512) {
            int r = idx >> 4, q = idx & 15;
            CP_ASYNC16(sb + SM_W1  + r*LDW + q*16, w1p  + idx*16);
            CP_ASYNC16(sb + SM_W2S + r*LDW + q*16, w2sp + idx*16);
            CP_ASYNC16(sb + SM_W2N + r*LDW + q*16, w2np + idx*16);
        }
        if (tid < 128) {
            ((float*)(sm + SM_B1))[tid] = b1_g[tid];
            ((float*)(sm + SM_B2))[tid] = b2_g[tid];
        }
        if (tid < 256) ((float*)(sm + SM_FC))[tid] = wfc_g[tid];
        ((float*)(sm + SM_PW))[tid] = g_pw[step*512 + tid];
        if (tid < 432) {                      // zero XR rows 136..147 (one-time)
            int r = 136 + tid/36, w = tid%36;
            *(uint32_t*)(sm + SM_XR + r*LDX + w*4) = 0;
        }
        // prefetch tile 0 Xs
        int r0 = blockIdx.x * 128;
        int n0 = r0 & (NV-1);
        int pbase = r0 - n0;
        for (int idx = tid; idx < 136*8; idx += 512) {
            int r = idx >> 3, q = idx & 7;
            int n = (n0 + r - 4 + NV) & (NV-1);
            CP_ASYNC16(sb + SM_XR + r*LDX + q*16,
                       (const char*)g_featb + ((size_t)(pbase + n)*64 + q*8)*2);
        }
        CP_COMMIT();
    }

    for (int t = 0; t < TILES_PER_CTA; t++) {
        int r0 = (t*GRID_C + blockIdx.x) * 128;
        int n0 = r0 & (NV-1);
        int pbase = r0 - n0;

        CP_WAIT0();
        __syncthreads();   // XR(t)+weights ready; prior tile fully done

        // poly rows -4..131 for this tile
        if (tid < 272) {
            int rr = tid >> 1, c = tid & 1;
            int g = pbase + ((n0 + rr - 4 + NV) & (NV-1));
            ((float*)(sm + SM_PP))[tid] = poly_in[(size_t)g*2 + c];
        }

        // ---- XN ring stencil only (rows 0..143), bf16x2 SIMD, uint2 grain ----
        for (int w = tid; w < 144*16; w += 512) {
            int r = w >> 4, j = w & 15;     // j = uint2 index (4 bf16)
            uint2 a = *(uint2*)(sm + SM_XR + (r  )*LDX + j*8);
            uint2 b = *(uint2*)(sm + SM_XR + (r+1)*LDX + j*8);
            uint2 c = *(uint2*)(sm + SM_XR + (r+3)*LDX + j*8);
            uint2 d = *(uint2*)(sm + SM_XR + (r+4)*LDX + j*8);
            *(uint2*)(sm + SM_XN + r*LDX + j*8) = ring4_bf16x4(a, b, c, d);
        }
        __syncthreads();   // XN ready (XR stays live through MMA1)

        // ---- MMA1: K=128 (kt<4 self from XR; kt>=4 ring from XN) ----
        float acc1[2][4][4];
        float accH[4][4];
        #pragma unroll
        for (int mf = 0; mf < 2; mf++)
            #pragma unroll
            for (int nf = 0; nf < 4; nf++)
                #pragma unroll
                for (int j = 0; j < 4; j++) { acc1[mf][nf][j] = 0.f; if (mf==0) accH[nf][j] = 0.f; }

        #pragma unroll
        for (int kt = 0; kt < 8; kt++) {
            uint32_t a[2][4], ah[4];
            #pragma unroll
            for (int mf = 0; mf < 2; mf++) {
                uint32_t arow = wm*32 + mf*16 + l7 + l8*8;
                uint32_t addr = (kt < 4)
                    ? sb + SM_XR + (2 + arow)*LDX + l16*16 + kt*32
                    : sb + SM_XN + arow*LDX + l16*16 + (kt-4)*32;
                ldmx4(a[mf], addr);
            }
            if (wm == 0) {
                uint32_t hrow = 128 + l7 + l8*8;
                uint32_t addr = (kt < 4)
                    ? sb + SM_XR + (2 + hrow)*LDX + l16*16 + kt*32
                    : sb + SM_XN + hrow*LDX + l16*16 + (kt-4)*32;
                ldmx4(ah, addr);
            }
            #pragma unroll
            for (int nf2 = 0; nf2 < 2; nf2++) {
                uint32_t b[4];
                ldmx4(b, sb + SM_W1 + (wn*32 + nf2*16 + l16*8 + l7)*LDW + kt*32 + l8*16);
                #pragma unroll
                for (int mf = 0; mf < 2; mf++) {
                    mma16816(acc1[mf][2*nf2],   a[mf], b[0], b[1]);
                    mma16816(acc1[mf][2*nf2+1], a[mf], b[2], b[3]);
                }
                if (wm == 0) {
                    mma16816(accH[2*nf2],   ah, b[0], b[1]);
                    mma16816(accH[2*nf2+1], ah, b[2], b[3]);
                }
            }
        }

        // ---- epilogue1 -> Hs (no sync needed: HS is a private region) ----
        {
            const float* PP = (const float*)(sm + SM_PP);
            const float* B  = (const float*)(sm + SM_B1);
            const float* PW = (const float*)(sm + SM_PW);
            int rlo = lane >> 2, qc = (lane & 3)*2;
            #pragma unroll
            for (int mf = 0; mf < 3; mf++) {
                if (mf == 2 && wm != 0) break;
                int hr = (mf == 2) ? (128 + rlo) : (wm*32 + mf*16 + rlo);
                bool v0 = (mf < 2) || (rlo < 4);
                bool v1 = (mf < 2);
                const float (*A0)[4] = (mf == 2) ? accH : acc1[mf];
                float px0=0,py0=0,ax0=0,ay0=0,px1=0,py1=0,ax1=0,ay1=0;
                if (v0) {
                    px0 = PP[(hr+2)*2]; py0 = PP[(hr+2)*2+1];
                    ax0 = 0.25f*(PP[hr*2]   + PP[(hr+1)*2]   + PP[(hr+3)*2]   + PP[(hr+4)*2]);
                    ay0 = 0.25f*(PP[hr*2+1] + PP[(hr+1)*2+1] + PP[(hr+3)*2+1] + PP[(hr+4)*2+1]);
                }
                int r1 = hr + 8;
                if (v1) {
                    px1 = PP[(r1+2)*2]; py1 = PP[(r1+2)*2+1];
                    ax1 = 0.25f*(PP[r1*2]   + PP[(r1+1)*2]   + PP[(r1+3)*2]   + PP[(r1+4)*2]);
                    ay1 = 0.25f*(PP[r1*2+1] + PP[(r1+1)*2+1] + PP[(r1+3)*2+1] + PP[(r1+4)*2+1]);
                }
                #pragma unroll
                for (int nf = 0; nf < 4; nf++) {
                    int n = wn*32 + nf*8 + qc;
                    float b0 = B[n],   w0x = PW[n],   w0y = PW[128+n],   w0ax = PW[256+n],   w0ay = PW[384+n];
                    float b1 = B[n+1], w1x = PW[n+1], w1y = PW[128+n+1], w1ax = PW[256+n+1], w1ay = PW[384+n+1];
                    if (v0) {
                        float v00 = A0[nf][0] + b0 + px0*w0x + py0*w0y + ax0*w0ax + ay0*w0ay;
                        float v01 = A0[nf][1] + b1 + px0*w1x + py0*w1y + ax0*w1ax + ay0*w1ay;
                        __nv_bfloat162 h0 = __float22bfloat162_rn(make_float2(fmaxf(v00,0.f), fmaxf(v01,0.f)));
                        *(uint32_t*)(sm + SM_HS + hr*LDW + n*2) = *(uint32_t*)&h0;
                    }
                    if (v1) {
                        float v10 = A0[nf][2] + b0 + px1*w0x + py1*w0y + ax1*w0ax + ay1*w0ay;
                        float v11 = A0[nf][3] + b1 + px1*w1x + py1*w1y + ax1*w1ax + ay1*w1ay;
                        __nv_bfloat162 h1 = __float22bfloat162_rn(make_float2(fmaxf(v10,0.f), fmaxf(v11,0.f)));
                        *(uint32_t*)(sm + SM_HS + r1*LDW + n*2) = *(uint32_t*)&h1;
                    }
                }
            }
        }
        __syncthreads();   // HS complete; XR now dead

        // ---- prefetch next tile's Xs into XR (overlaps Hn/MMA2/epi2) ----
        if (t + 1 < TILES_PER_CTA) {
            int r0n = ((t+1)*GRID_C + blockIdx.x) * 128;
            int n0n = r0n & (NV-1);
            int pbn = r0n - n0n;
            for (int idx = tid; idx < 136*8; idx += 512) {
                int r = idx >> 3, q = idx & 7;
                int n = (n0n + r - 4 + NV) & (NV-1);
                CP_ASYNC16(sb + SM_XR + r*LDX + q*16,
                           (const char*)g_featb + ((size_t)(pbn + n)*64 + q*8)*2);
            }
            CP_COMMIT();
        }

        // ---- Hn ring stencil (rows 0..127), bf16x2 SIMD ----
        for (int w = tid; w < 128*32; w += 512) {
            int r = w >> 5, j = w & 31;
            uint2 a = *(uint2*)(sm + SM_HS + (r  )*LDW + j*8);
            uint2 b = *(uint2*)(sm + SM_HS + (r+1)*LDW + j*8);
            uint2 c = *(uint2*)(sm + SM_HS + (r+3)*LDW + j*8);
            uint2 d = *(uint2*)(sm + SM_HS + (r+4)*LDW + j*8);
            *(uint2*)(sm + SM_HN + r*LDW + j*8) = ring4_bf16x4(a, b, c, d);
        }
        __syncthreads();

        // ---- MMA2: merged single loop (self + neighbor interleaved) ----
        float acc2[2][4][4];
        #pragma unroll
        for (int mf = 0; mf < 2; mf++)
            #pragma unroll
            for (int nf = 0; nf < 4; nf++)
                #pragma unroll
                for (int j = 0; j < 4; j++) acc2[mf][nf][j] = 0.f;

        #pragma unroll
        for (int kt = 0; kt < 8; kt++) {
            uint32_t as[2][4], an[2][4];
            #pragma unroll
            for (int mf = 0; mf < 2; mf++) {
                ldmx4(as[mf], sb + SM_HS + (2 + wm*32 + mf*16 + l7 + l8*8)*LDW + l16*16 + kt*32);
                ldmx4(an[mf], sb + SM_HN + (    wm*32 + mf*16 + l7 + l8*8)*LDW + l16*16 + kt*32);
            }
            #pragma unroll
            for (int nf2 = 0; nf2 < 2; nf2++) {
                uint32_t bs[4], bn[4];
                ldmx4(bs, sb + SM_W2S + (wn*32 + nf2*16 + l16*8 + l7)*LDW + kt*32 + l8*16);
                ldmx4(bn, sb + SM_W2N + (wn*32 + nf2*16 + l16*8 + l7)*LDW + kt*32 + l8*16);
                #pragma unroll
                for (int mf = 0; mf < 2; mf++) {
                    mma16816(acc2[mf][2*nf2],   as[mf], bs[0], bs[1]);
                    mma16816(acc2[mf][2*nf2+1], as[mf], bs[2], bs[3]);
                    mma16816(acc2[mf][2*nf2],   an[mf], bn[0], bn[1]);
                    mma16816(acc2[mf][2*nf2+1], an[mf], bn[2], bn[3]);
                }
            }
        }

        // ---- relu + FC(128->2) + poly update ----
        {
            const float* B  = (const float*)(sm + SM_B2);
            const float* FC = (const float*)(sm + SM_FC);
            int rlo = lane >> 2, qc = (lane & 3)*2;
            float pr[2][2][2];
            #pragma unroll
            for (int mf = 0; mf < 2; mf++)
                #pragma unroll
                for (int rh = 0; rh < 2; rh++) { pr[mf][rh][0] = 0.f; pr[mf][rh][1] = 0.f; }
            #pragma unroll
            for (int mf = 0; mf < 2; mf++)
                #pragma unroll
                for (int nf = 0; nf < 4; nf++) {
                    int n = wn*32 + nf*8 + qc;
                    float b0 = B[n], b1 = B[n+1];
                    float h00 = fmaxf(acc2[mf][nf][0] + b0, 0.f);
                    float h01 = fmaxf(acc2[mf][nf][1] + b1, 0.f);
                    float h10 = fmaxf(acc2[mf][nf][2] + b0, 0.f);
                    float h11 = fmaxf(acc2[mf][nf][3] + b1, 0.f);
                    float f0x = FC[n*2], f0y = FC[n*2+1], f1x = FC[(n+1)*2], f1y = FC[(n+1)*2+1];
                    pr[mf][0][0] += h00*f0x + h01*f1x;  pr[mf][0][1] += h00*f0y + h01*f1y;
                    pr[mf][1][0] += h10*f0x + h11*f1x;  pr[mf][1][1] += h10*f0y + h11*f1y;
                }
            #pragma unroll
            for (int mf = 0; mf < 2; mf++)
                #pragma unroll
                for (int rh = 0; rh < 2; rh++)
                    #pragma unroll
                    for (int j = 0; j < 2; j++) {
                        pr[mf][rh][j] += __shfl_xor_sync(0xffffffffu, pr[mf][rh][j], 1);
                        pr[mf][rh][j] += __shfl_xor_sync(0xffffffffu, pr[mf][rh][j], 2);
                    }
            float* RED = (float*)(sm + SM_RED);
            if ((lane & 3) == 0) {
                #pragma unroll
                for (int mf = 0; mf < 2; mf++)
                    #pragma unroll
                    for (int rh = 0; rh < 2; rh++) {
                        int row = wm*32 + mf*16 + rh*8 + rlo;
                        RED[row*8 + wn*2 + 0] = pr[mf][rh][0];
                        RED[row*8 + wn*2 + 1] = pr[mf][rh][1];
                    }
            }
            __syncthreads();
            if (tid < 256) {
                int row = tid >> 1, j = tid & 1;
                float s = RED[row*8 + j] + RED[row*8 + 2 + j]
                        + RED[row*8 + 4 + j] + RED[row*8 + 6 + j] + bfc_g[j];
                poly_out[(size_t)(r0 + row)*2 + j] =
                    ((const float*)(sm + SM_PP))[(row + 4)*2 + j] + s;
            }
        }
    }
}

// ---------------------------------------------------------------------------
extern "C" void kernel_launch(void* const* d_in, const int* in_sizes, int n_in,
                              void* d_out, int out_size)
{
    const float* feature    = (const float*)d_in[0];
    const float* init_polys = (const float*)d_in[1];
    /* d_in[2] = adj (fixed ring graph -> stencil) */
    const float* W1s = (const float*)d_in[3];
    const float* W1n = (const float*)d_in[4];
    const float* b1  = (const float*)d_in[5];
    const float* W2s = (const float*)d_in[6];
    const float* W2n = (const float*)d_in[7];
    const float* b2  = (const float*)d_in[8];
    const float* Wfc = (const float*)d_in[9];
    const float* bfc = (const float*)d_in[10];

    cudaFuncSetAttribute(gemm12_kernel, cudaFuncAttributeMaxDynamicSharedMemorySize, SM_TOTAL);

    float *polyA, *polyB;
    cudaGetSymbolAddress((void**)&polyA, g_polyA);
    cudaGetSymbolAddress((void**)&polyB, g_polyB);

    prep_kernel<<<3, 256>>>(W1s, W1n, W2s, W2n);

    float* pouts[3] = { polyA, polyB, (float*)d_out };
    const float* pin = init_polys;
    for (int i = 0; i < 3; i++) {
        sample_kernel<<<M/32, dim3(8,32)>>>(feature, pin, i);
        gemm12_kernel<<<GRID_C, 512, SM_TOTAL>>>(pin, pouts[i],
                                                 b1 + i*S, b2 + i*S,
                                                 Wfc + i*S*2, bfc + i*2, i);
        pin = pouts[i];
    }
}